// round 7
// baseline (speedup 1.0000x reference)
#include <cuda_runtime.h>

#define NMAX 100000
#define CDIM 64
#define NSN 16

// ---- scratch (device globals; no allocation allowed) ----
__device__ float g_xq[NMAX * CDIM];
__device__ float g_kv[NMAX * 128];   // interleaved: [n][c*2] = k, [n][c*2+1] = v

// ---------------------------------------------------------------------------
// Kernel 1: y_{q,k,v} = x @ W^T + b.
// ---------------------------------------------------------------------------
__global__ __launch_bounds__(256) void proj3_kernel(
    const float* __restrict__ x,
    const float* __restrict__ Wq, const float* __restrict__ bq,
    const float* __restrict__ Wk, const float* __restrict__ bk,
    const float* __restrict__ Wv, const float* __restrict__ bv, int n)
{
    __shared__ __align__(16) float xsT[64][68];
    __shared__ __align__(16) float WT[64][68];
    __shared__ float bias[64];

    int t = threadIdx.x;
    int row0 = blockIdx.x * 64;

    for (int i = t; i < 64 * 64; i += 256) {
        int r = i >> 6, k = i & 63;
        int rr = row0 + r;
        xsT[k][r] = (rr < n) ? x[rr * 64 + k] : 0.f;
    }

    int tx = t & 15;
    int ty = t >> 4;

    const float* Ws[3] = { Wq, Wk, Wv };
    const float* bs[3] = { bq, bk, bv };

#pragma unroll
    for (int m = 0; m < 3; m++) {
        __syncthreads();
        for (int i = t; i < 64 * 64; i += 256) {
            int c = i >> 6, k = i & 63;
            WT[k][c] = Ws[m][i];
        }
        if (t < 64) bias[t] = bs[m][t];
        __syncthreads();

        float acc[4][4];
#pragma unroll
        for (int i = 0; i < 4; i++)
#pragma unroll
            for (int j = 0; j < 4; j++) acc[i][j] = 0.f;

#pragma unroll 8
        for (int k = 0; k < 64; k++) {
            float4 a4 = *(const float4*)&xsT[k][ty * 4];
            float4 b4 = *(const float4*)&WT[k][tx * 4];
            float a[4] = { a4.x, a4.y, a4.z, a4.w };
            float b[4] = { b4.x, b4.y, b4.z, b4.w };
#pragma unroll
            for (int i = 0; i < 4; i++)
#pragma unroll
                for (int j = 0; j < 4; j++)
                    acc[i][j] = fmaf(a[i], b[j], acc[i][j]);
        }

#pragma unroll
        for (int i = 0; i < 4; i++) {
            int r = row0 + ty * 4 + i;
            if (r < n) {
#pragma unroll
                for (int j = 0; j < 4; j++) {
                    int cc = tx * 4 + j;
                    float val = acc[i][j] + bias[cc];
                    if (m == 0)      g_xq[r * 64 + cc] = val;
                    else             g_kv[r * 128 + cc * 2 + (m - 1)] = val;
                }
            }
        }
    }
}

// ---------------------------------------------------------------------------
// Kernel 2: fused attention. 4 points/block, 64 threads/point.
// B1 (16x8 @ 64 reduction) done register-resident via warp butterfly shuffles.
// ---------------------------------------------------------------------------
__global__ __launch_bounds__(256, 3) void attn_kernel(
    const float* __restrict__ p, const int* __restrict__ idx,
    const float* __restrict__ pw1, const float* __restrict__ pb1,
    const float* __restrict__ pbng, const float* __restrict__ pbnb,
    const float* __restrict__ pbnm, const float* __restrict__ pbnv,
    const float* __restrict__ pw2, const float* __restrict__ pb2,
    const float* __restrict__ bn1g, const float* __restrict__ bn1b,
    const float* __restrict__ bn1m, const float* __restrict__ bn1v,
    const float* __restrict__ ww1, const float* __restrict__ wb1,
    const float* __restrict__ bn2g, const float* __restrict__ bn2b,
    const float* __restrict__ bn2m, const float* __restrict__ bn2v,
    const float* __restrict__ ww2, const float* __restrict__ wb2,
    float* __restrict__ out, int n)
{
    __shared__ __align__(16) float s_uh[4][2][16][8];  // per-half partial u sums
    __shared__ float s_lg[4][16][9];                   // logits, stride 9
    __shared__ __align__(16) int   s_j[4][16];
    __shared__ __align__(16) float4 s_pr4[4][16];      // post-ReLU p_r (x,y,z,-)
    __shared__ float s_pw2[64][3];
    __shared__ float s_sc1[64], s_sh1[64], s_pb2[64];
    __shared__ __align__(16) float s_w2T[8][8];        // w_w2 transposed
    __shared__ float s_b1[8], s_sc2[8], s_sh2[8], s_b2[8];
    __shared__ float s_pw1[9], s_pb1[3], s_psc[3], s_psh[3];

    int t = threadIdx.x;

    // ---- fold BN params + stage small tensors ----
    if (t < 64) {
        float sc = bn1g[t] * rsqrtf(bn1v[t] + 1e-5f);
        s_sc1[t] = sc;
        s_sh1[t] = bn1b[t] - bn1m[t] * sc;
        s_pb2[t] = pb2[t];
        s_pw2[t][0] = pw2[t * 3 + 0];
        s_pw2[t][1] = pw2[t * 3 + 1];
        s_pw2[t][2] = pw2[t * 3 + 2];
    } else if (t < 72) {
        int q = t - 64;
        float sc = bn2g[q] * rsqrtf(bn2v[q] + 1e-5f);
        s_sc2[q] = sc;
        s_sh2[q] = bn2b[q] - bn2m[q] * sc;
        s_b1[q] = wb1[q];
        s_b2[q] = wb2[q];
    } else if (t >= 128 && t < 192) {
        int q = t - 128;
        int k = q >> 3, j = q & 7;
        s_w2T[k][j] = ww2[j * 8 + k];
    } else if (t >= 192 && t < 207) {
        int q = t - 192;
        if (q < 9) s_pw1[q] = pw1[q];
        else if (q < 12) s_pb1[q - 9] = pb1[q - 9];
        else {
            int k = q - 12;
            float sc = pbng[k] * rsqrtf(pbnv[k] + 1e-5f);
            s_psc[k] = sc;
            s_psh[k] = pbnb[k] - pbnm[k] * sc;
        }
    }
    __syncthreads();

    int pt = t >> 6;          // point slot (0..3)
    int c  = t & 63;          // channel
    int l  = t & 31;          // lane
    int h  = (t >> 5) & 1;    // channel half
    int pid = blockIdx.x * 4 + pt;
    bool valid = pid < n;
    int n0 = valid ? pid : 0;

    // per-lane w1 column (8 loads; 2KB tensor -> L1-resident)
    float w1col[8];
#pragma unroll
    for (int j = 0; j < 8; j++) w1col[j] = ww1[j * 64 + c];

    // ---- Phase A0: 16 threads/point: idx row + p_r 3-vec ----
    if (c < 16) {
        int j = idx[n0 * 16 + c];
        s_j[pt][c] = j;
        float px = p[n0 * 3 + 0], py = p[n0 * 3 + 1], pz = p[n0 * 3 + 2];
        float dx = p[j * 3 + 0] - px;
        float dy = p[j * 3 + 1] - py;
        float dz = p[j * 3 + 2] - pz;
        float r0 = fmaf(s_pw1[0], dx, fmaf(s_pw1[1], dy, fmaf(s_pw1[2], dz, s_pb1[0])));
        float r1 = fmaf(s_pw1[3], dx, fmaf(s_pw1[4], dy, fmaf(s_pw1[5], dz, s_pb1[1])));
        float r2 = fmaf(s_pw1[6], dx, fmaf(s_pw1[7], dy, fmaf(s_pw1[8], dz, s_pb1[2])));
        float4 rr;
        rr.x = fmaxf(fmaf(r0, s_psc[0], s_psh[0]), 0.f);
        rr.y = fmaxf(fmaf(r1, s_psc[1], s_psh[1]), 0.f);
        rr.z = fmaxf(fmaf(r2, s_psc[2], s_psh[2]), 0.f);
        rr.w = 0.f;
        s_pr4[pt][c] = rr;
    }
    __syncthreads();

    float xqc = g_xq[n0 * 64 + c];
    float sc1 = s_sc1[c], sh1 = s_sh1[c];
    float w2a = s_pw2[c][0], w2b = s_pw2[c][1], w2c = s_pw2[c][2];
    float pb2c = s_pb2[c];

    // ---- Phase A1: gather (k,v) in two 8-neighbor halves; wreg/vpr in regs ----
    float wreg[16];
    float vpr[16];
    int c2 = c * 2;
#pragma unroll
    for (int hh = 0; hh < 2; hh++) {
        int js[8];
        {
            const int4* jp = (const int4*)&s_j[pt][hh * 8];
            int4 v0 = jp[0], v1 = jp[1];
            js[0] = v0.x; js[1] = v0.y; js[2] = v0.z; js[3] = v0.w;
            js[4] = v1.x; js[5] = v1.y; js[6] = v1.z; js[7] = v1.w;
        }
        float2 kv[8];
#pragma unroll
        for (int q = 0; q < 8; q++)
            kv[q] = *(const float2*)&g_kv[js[q] * 128 + c2];
#pragma unroll
        for (int q = 0; q < 8; q++) {
            int nb = hh * 8 + q;
            float4 rr = s_pr4[pt][nb];
            float pr = fmaf(w2a, rr.x, fmaf(w2b, rr.y, fmaf(w2c, rr.z, pb2c)));
            float w = kv[q].x - xqc + pr;
            wreg[nb] = fmaxf(fmaf(w, sc1, sh1), 0.f);
            vpr[nb] = kv[q].y + pr;
        }
    }

    // ---- Phase B1: warp butterfly: u_half[nb][j] = sum_lane wreg[nb]*w1col[j] ----
    {
        bool hi4 = (l & 16) != 0;
        bool hi3 = (l & 8) != 0;
        bool hi2 = (l & 4) != 0;
        int jw = l >> 2;
        bool writer = (l & 3) == 0;
#pragma unroll
        for (int nb = 0; nb < 16; nb++) {
            float x = wreg[nb];
            float pp[8];
#pragma unroll
            for (int j = 0; j < 8; j++) pp[j] = x * w1col[j];
            float q[4];
#pragma unroll
            for (int i = 0; i < 4; i++) {
                float snd = hi4 ? pp[i] : pp[i + 4];
                float rcv = __shfl_xor_sync(0xffffffffu, snd, 16);
                q[i] = (hi4 ? pp[i + 4] : pp[i]) + rcv;
            }
            float r[2];
#pragma unroll
            for (int i = 0; i < 2; i++) {
                float snd = hi3 ? q[i] : q[i + 2];
                float rcv = __shfl_xor_sync(0xffffffffu, snd, 8);
                r[i] = (hi3 ? q[i + 2] : q[i]) + rcv;
            }
            float snd = hi2 ? r[0] : r[1];
            float rcv = __shfl_xor_sync(0xffffffffu, snd, 4);
            float s = (hi2 ? r[1] : r[0]) + rcv;
            s += __shfl_xor_sync(0xffffffffu, s, 2);
            s += __shfl_xor_sync(0xffffffffu, s, 1);
            if (writer) s_uh[pt][h][nb][jw] = s;
        }
    }
    __syncthreads();

    // ---- Phase B2: u = relu(bn2(uh0+uh1+b1)); logits = u @ w_w2^T + b2 ----
    {
        int nb = c >> 2;
        int j0 = (c & 3) * 2;
        const float4* u0p = (const float4*)s_uh[pt][0][nb];
        const float4* u1p = (const float4*)s_uh[pt][1][nb];
        float4 x0 = u0p[0], x1 = u0p[1];
        float4 y0 = u1p[0], y1 = u1p[1];
        float uu[8] = { x0.x + y0.x, x0.y + y0.y, x0.z + y0.z, x0.w + y0.w,
                        x1.x + y1.x, x1.y + y1.y, x1.z + y1.z, x1.w + y1.w };
        float a0 = s_b2[j0], a1 = s_b2[j0 + 1];
#pragma unroll
        for (int k = 0; k < 8; k++) {
            float u = fmaxf(fmaf(uu[k] + s_b1[k], s_sc2[k], s_sh2[k]), 0.f);
            float2 qv = *(const float2*)&s_w2T[k][j0];
            a0 = fmaf(u, qv.x, a0);
            a1 = fmaf(u, qv.y, a1);
        }
        s_lg[pt][nb][j0] = a0;
        s_lg[pt][nb][j0 + 1] = a1;
    }
    __syncthreads();

    // ---- Phase C: softmax over neighbors ----
    if (c < 8) {
        int j = c;
        float m = -1e30f;
#pragma unroll
        for (int nb = 0; nb < 16; nb++) m = fmaxf(m, s_lg[pt][nb][j]);
        float e[16];
        float sum = 0.f;
#pragma unroll
        for (int nb = 0; nb < 16; nb++) {
            e[nb] = __expf(s_lg[pt][nb][j] - m);
            sum += e[nb];
        }
        float inv = 1.f / sum;
#pragma unroll
        for (int nb = 0; nb < 16; nb++) s_lg[pt][nb][j] = e[nb] * inv;
    }
    __syncthreads();

    // ---- Phase D: out[c] = sum_nb vpr[nb] * w[nb][c%8] ----
    if (valid) {
        int j = c & 7;
        float acc = 0.f;
#pragma unroll
        for (int nb = 0; nb < 16; nb++)
            acc = fmaf(vpr[nb], s_lg[pt][nb][j], acc);
        out[pid * 64 + c] = acc;
    }
}

// ---------------------------------------------------------------------------
extern "C" void kernel_launch(void* const* d_in, const int* in_sizes, int n_in,
                              void* d_out, int out_size)
{
    const float* p    = (const float*)d_in[0];
    const float* x    = (const float*)d_in[1];
    const int*   idx  = (const int*)d_in[2];
    const float* Wq   = (const float*)d_in[3];
    const float* bq   = (const float*)d_in[4];
    const float* Wk   = (const float*)d_in[5];
    const float* bk   = (const float*)d_in[6];
    const float* Wv   = (const float*)d_in[7];
    const float* bv   = (const float*)d_in[8];
    const float* pw1  = (const float*)d_in[9];
    const float* pb1  = (const float*)d_in[10];
    const float* pbng = (const float*)d_in[11];
    const float* pbnb = (const float*)d_in[12];
    const float* pbnm = (const float*)d_in[13];
    const float* pbnv = (const float*)d_in[14];
    const float* pw2  = (const float*)d_in[15];
    const float* pb2  = (const float*)d_in[16];
    const float* bn1g = (const float*)d_in[17];
    const float* bn1b = (const float*)d_in[18];
    const float* bn1m = (const float*)d_in[19];
    const float* bn1v = (const float*)d_in[20];
    const float* ww1  = (const float*)d_in[21];
    const float* wb1  = (const float*)d_in[22];
    const float* bn2g = (const float*)d_in[23];
    const float* bn2b = (const float*)d_in[24];
    const float* bn2m = (const float*)d_in[25];
    const float* bn2v = (const float*)d_in[26];
    const float* ww2  = (const float*)d_in[27];
    const float* wb2  = (const float*)d_in[28];

    int n = in_sizes[0] / 3;
    float* out = (float*)d_out;

    proj3_kernel<<<(n + 63) / 64, 256>>>(x, Wq, bq, Wk, bk, Wv, bv, n);
    attn_kernel<<<(n + 3) / 4, 256>>>(
        p, idx, pw1, pb1, pbng, pbnb, pbnm, pbnv, pw2, pb2,
        bn1g, bn1b, bn1m, bn1v, ww1, wb1,
        bn2g, bn2b, bn2m, bn2v, ww2, wb2,
        out, n);
}

// round 8
// speedup vs baseline: 1.0730x; 1.0730x over previous
#include <cuda_runtime.h>

#define NMAX 100000
#define CDIM 64
#define NSN 16

// ---- scratch (device globals; no allocation allowed) ----
__device__ float g_xq[NMAX * CDIM];
__device__ float g_kv[NMAX * 128];   // interleaved: [n][c*2] = k, [n][c*2+1] = v

// ---------------------------------------------------------------------------
// Kernel 1: y_{q,k,v} = x @ W^T + b.
// ---------------------------------------------------------------------------
__global__ __launch_bounds__(256) void proj3_kernel(
    const float* __restrict__ x,
    const float* __restrict__ Wq, const float* __restrict__ bq,
    const float* __restrict__ Wk, const float* __restrict__ bk,
    const float* __restrict__ Wv, const float* __restrict__ bv, int n)
{
    __shared__ __align__(16) float xsT[64][68];
    __shared__ __align__(16) float WT[64][68];
    __shared__ float bias[64];

    int t = threadIdx.x;
    int row0 = blockIdx.x * 64;

    for (int i = t; i < 64 * 64; i += 256) {
        int r = i >> 6, k = i & 63;
        int rr = row0 + r;
        xsT[k][r] = (rr < n) ? x[rr * 64 + k] : 0.f;
    }

    int tx = t & 15;
    int ty = t >> 4;

    const float* Ws[3] = { Wq, Wk, Wv };
    const float* bs[3] = { bq, bk, bv };

#pragma unroll
    for (int m = 0; m < 3; m++) {
        __syncthreads();
        for (int i = t; i < 64 * 64; i += 256) {
            int c = i >> 6, k = i & 63;
            WT[k][c] = Ws[m][i];
        }
        if (t < 64) bias[t] = bs[m][t];
        __syncthreads();

        float acc[4][4];
#pragma unroll
        for (int i = 0; i < 4; i++)
#pragma unroll
            for (int j = 0; j < 4; j++) acc[i][j] = 0.f;

#pragma unroll 8
        for (int k = 0; k < 64; k++) {
            float4 a4 = *(const float4*)&xsT[k][ty * 4];
            float4 b4 = *(const float4*)&WT[k][tx * 4];
            float a[4] = { a4.x, a4.y, a4.z, a4.w };
            float b[4] = { b4.x, b4.y, b4.z, b4.w };
#pragma unroll
            for (int i = 0; i < 4; i++)
#pragma unroll
                for (int j = 0; j < 4; j++)
                    acc[i][j] = fmaf(a[i], b[j], acc[i][j]);
        }

#pragma unroll
        for (int i = 0; i < 4; i++) {
            int r = row0 + ty * 4 + i;
            if (r < n) {
#pragma unroll
                for (int j = 0; j < 4; j++) {
                    int cc = tx * 4 + j;
                    float val = acc[i][j] + bias[cc];
                    if (m == 0)      g_xq[r * 64 + cc] = val;
                    else             g_kv[r * 128 + cc * 2 + (m - 1)] = val;
                }
            }
        }
    }
}

// ---------------------------------------------------------------------------
// Kernel 2: fused attention. 4 points/block, 64 threads/point.
// B1: warp = (point, nb-half); lane = (j, c-quarter); w1 reg-resident,
// wbuf reads 8-way broadcast + rotated-phase conflict-free; 2 SHFL per nb.
// ---------------------------------------------------------------------------
__global__ __launch_bounds__(256, 4) void attn_kernel(
    const float* __restrict__ p, const int* __restrict__ idx,
    const float* __restrict__ pw1, const float* __restrict__ pb1,
    const float* __restrict__ pbng, const float* __restrict__ pbnb,
    const float* __restrict__ pbnm, const float* __restrict__ pbnv,
    const float* __restrict__ pw2, const float* __restrict__ pb2,
    const float* __restrict__ bn1g, const float* __restrict__ bn1b,
    const float* __restrict__ bn1m, const float* __restrict__ bn1v,
    const float* __restrict__ ww1, const float* __restrict__ wb1,
    const float* __restrict__ bn2g, const float* __restrict__ bn2b,
    const float* __restrict__ bn2m, const float* __restrict__ bn2v,
    const float* __restrict__ ww2, const float* __restrict__ wb2,
    float* __restrict__ out, int n)
{
    __shared__ __align__(16) float s_wbuf[4][16][68];  // relu(bn1(w)), stride 68
    __shared__ __align__(16) float s_u[4][16][12];     // post-bn2 u, stride 12
    __shared__ float s_lg[4][16][9];                   // logits, stride 9
    __shared__ __align__(16) int   s_j[4][16];
    __shared__ __align__(16) float4 s_pr4[4][16];      // post-ReLU p_r (x,y,z,-)
    __shared__ __align__(16) float s_w1J[8][68];       // ww1 rows (j-major), pad 68
    __shared__ float s_pw2[64][3];
    __shared__ float s_sc1[64], s_sh1[64], s_pb2[64];
    __shared__ __align__(16) float s_w2T[8][8];        // w_w2 transposed
    __shared__ float s_b1[8], s_sc2[8], s_sh2[8], s_b2[8];
    __shared__ float s_pw1[9], s_pb1[3], s_psc[3], s_psh[3];

    int t = threadIdx.x;

    // ---- fold BN params + stage small tensors ----
    if (t < 64) {
        float sc = bn1g[t] * rsqrtf(bn1v[t] + 1e-5f);
        s_sc1[t] = sc;
        s_sh1[t] = bn1b[t] - bn1m[t] * sc;
        s_pb2[t] = pb2[t];
#pragma unroll
        for (int j = 0; j < 8; j++) s_w1J[j][t] = ww1[j * 64 + t];
        s_pw2[t][0] = pw2[t * 3 + 0];
        s_pw2[t][1] = pw2[t * 3 + 1];
        s_pw2[t][2] = pw2[t * 3 + 2];
    } else if (t < 72) {
        int q = t - 64;
        float sc = bn2g[q] * rsqrtf(bn2v[q] + 1e-5f);
        s_sc2[q] = sc;
        s_sh2[q] = bn2b[q] - bn2m[q] * sc;
        s_b1[q] = wb1[q];
        s_b2[q] = wb2[q];
    } else if (t >= 128 && t < 192) {
        int q = t - 128;
        int k = q >> 3, j = q & 7;
        s_w2T[k][j] = ww2[j * 8 + k];
    } else if (t >= 192 && t < 207) {
        int q = t - 192;
        if (q < 9) s_pw1[q] = pw1[q];
        else if (q < 12) s_pb1[q - 9] = pb1[q - 9];
        else {
            int k = q - 12;
            float sc = pbng[k] * rsqrtf(pbnv[k] + 1e-5f);
            s_psc[k] = sc;
            s_psh[k] = pbnb[k] - pbnm[k] * sc;
        }
    }
    __syncthreads();

    int pt = t >> 6;          // point slot (0..3)
    int c  = t & 63;          // channel
    int l  = t & 31;          // lane
    int pid = blockIdx.x * 4 + pt;
    bool valid = pid < n;
    int n0 = valid ? pid : 0;

    // ---- Phase A0: 16 threads/point: idx row + p_r 3-vec ----
    if (c < 16) {
        int j = idx[n0 * 16 + c];
        s_j[pt][c] = j;
        float px = p[n0 * 3 + 0], py = p[n0 * 3 + 1], pz = p[n0 * 3 + 2];
        float dx = p[j * 3 + 0] - px;
        float dy = p[j * 3 + 1] - py;
        float dz = p[j * 3 + 2] - pz;
        float r0 = fmaf(s_pw1[0], dx, fmaf(s_pw1[1], dy, fmaf(s_pw1[2], dz, s_pb1[0])));
        float r1 = fmaf(s_pw1[3], dx, fmaf(s_pw1[4], dy, fmaf(s_pw1[5], dz, s_pb1[1])));
        float r2 = fmaf(s_pw1[6], dx, fmaf(s_pw1[7], dy, fmaf(s_pw1[8], dz, s_pb1[2])));
        float4 rr;
        rr.x = fmaxf(fmaf(r0, s_psc[0], s_psh[0]), 0.f);
        rr.y = fmaxf(fmaf(r1, s_psc[1], s_psh[1]), 0.f);
        rr.z = fmaxf(fmaf(r2, s_psc[2], s_psh[2]), 0.f);
        rr.w = 0.f;
        s_pr4[pt][c] = rr;
    }
    __syncthreads();

    float xqc = g_xq[n0 * 64 + c];
    float sc1 = s_sc1[c], sh1 = s_sh1[c];
    float w2a = s_pw2[c][0], w2b = s_pw2[c][1], w2c = s_pw2[c][2];
    float pb2c = s_pb2[c];

    // ---- Phase A1: gather (k,v) in two 8-neighbor halves ----
    float vpr[16];
    int c2 = c * 2;
#pragma unroll
    for (int hh = 0; hh < 2; hh++) {
        int js[8];
        {
            const int4* jp = (const int4*)&s_j[pt][hh * 8];
            int4 v0 = jp[0], v1 = jp[1];
            js[0] = v0.x; js[1] = v0.y; js[2] = v0.z; js[3] = v0.w;
            js[4] = v1.x; js[5] = v1.y; js[6] = v1.z; js[7] = v1.w;
        }
        float2 kv[8];
#pragma unroll
        for (int q = 0; q < 8; q++)
            kv[q] = *(const float2*)&g_kv[js[q] * 128 + c2];
#pragma unroll
        for (int q = 0; q < 8; q++) {
            int nb = hh * 8 + q;
            float4 rr = s_pr4[pt][nb];
            float pr = fmaf(w2a, rr.x, fmaf(w2b, rr.y, fmaf(w2c, rr.z, pb2c)));
            float w = kv[q].x - xqc + pr;
            s_wbuf[pt][nb][c] = fmaxf(fmaf(w, sc1, sh1), 0.f);
            vpr[nb] = kv[q].y + pr;
        }
    }
    __syncthreads();

    // ---- Phase B1: warp = (point, nb-half); lane = (j = l>>2, q = l&3) ----
    {
        int w   = t >> 5;         // warp 0..7
        int bpt = w >> 1;         // point this warp serves
        int hh  = w & 1;          // neighbor half
        int j   = l >> 2;         // output channel 0..7
        int q   = l & 3;          // c-quarter

        // preload w1 quarter into regs (rotated phase for conflict-free wbuf reads)
        float4 w1q[4];
#pragma unroll
        for (int i = 0; i < 4; i++) {
            int ii = (i + q) & 3;
            w1q[i] = *(const float4*)&s_w1J[j][q * 16 + ii * 4];
        }

        float b1j = s_b1[j], sc2j = s_sc2[j], sh2j = s_sh2[j];

#pragma unroll
        for (int nbq = 0; nbq < 8; nbq++) {
            int nb = hh * 8 + nbq;
            const float* row = s_wbuf[bpt][nb];
            float acc = 0.f;
#pragma unroll
            for (int i = 0; i < 4; i++) {
                int ii = (i + q) & 3;
                float4 wv = *(const float4*)&row[q * 16 + ii * 4];
                float4 qw = w1q[i];
                acc = fmaf(wv.x, qw.x, acc);
                acc = fmaf(wv.y, qw.y, acc);
                acc = fmaf(wv.z, qw.z, acc);
                acc = fmaf(wv.w, qw.w, acc);
            }
            acc += __shfl_xor_sync(0xffffffffu, acc, 1);
            acc += __shfl_xor_sync(0xffffffffu, acc, 2);
            if (q == 0)
                s_u[bpt][nb][j] = fmaxf(fmaf(acc + b1j, sc2j, sh2j), 0.f);
        }
    }
    __syncthreads();

    // ---- Phase B2: logits = u @ w_w2^T + b2 ----
    {
        int nb = c >> 2;
        int j0 = (c & 3) * 2;
        const float4* up = (const float4*)s_u[pt][nb];
        float4 u0 = up[0], u1 = up[1];
        float uu[8] = { u0.x, u0.y, u0.z, u0.w, u1.x, u1.y, u1.z, u1.w };
        float a0 = s_b2[j0], a1 = s_b2[j0 + 1];
#pragma unroll
        for (int k = 0; k < 8; k++) {
            float2 qv = *(const float2*)&s_w2T[k][j0];
            a0 = fmaf(uu[k], qv.x, a0);
            a1 = fmaf(uu[k], qv.y, a1);
        }
        s_lg[pt][nb][j0] = a0;
        s_lg[pt][nb][j0 + 1] = a1;
    }
    __syncthreads();

    // ---- Phase C: softmax over neighbors ----
    if (c < 8) {
        int j = c;
        float m = -1e30f;
#pragma unroll
        for (int nb = 0; nb < 16; nb++) m = fmaxf(m, s_lg[pt][nb][j]);
        float e[16];
        float sum = 0.f;
#pragma unroll
        for (int nb = 0; nb < 16; nb++) {
            e[nb] = __expf(s_lg[pt][nb][j] - m);
            sum += e[nb];
        }
        float inv = 1.f / sum;
#pragma unroll
        for (int nb = 0; nb < 16; nb++) s_lg[pt][nb][j] = e[nb] * inv;
    }
    __syncthreads();

    // ---- Phase D: out[c] = sum_nb vpr[nb] * w[nb][c%8] ----
    if (valid) {
        int j = c & 7;
        float acc = 0.f;
#pragma unroll
        for (int nb = 0; nb < 16; nb++)
            acc = fmaf(vpr[nb], s_lg[pt][nb][j], acc);
        out[pid * 64 + c] = acc;
    }
}

// ---------------------------------------------------------------------------
extern "C" void kernel_launch(void* const* d_in, const int* in_sizes, int n_in,
                              void* d_out, int out_size)
{
    const float* p    = (const float*)d_in[0];
    const float* x    = (const float*)d_in[1];
    const int*   idx  = (const int*)d_in[2];
    const float* Wq   = (const float*)d_in[3];
    const float* bq   = (const float*)d_in[4];
    const float* Wk   = (const float*)d_in[5];
    const float* bk   = (const float*)d_in[6];
    const float* Wv   = (const float*)d_in[7];
    const float* bv   = (const float*)d_in[8];
    const float* pw1  = (const float*)d_in[9];
    const float* pb1  = (const float*)d_in[10];
    const float* pbng = (const float*)d_in[11];
    const float* pbnb = (const float*)d_in[12];
    const float* pbnm = (const float*)d_in[13];
    const float* pbnv = (const float*)d_in[14];
    const float* pw2  = (const float*)d_in[15];
    const float* pb2  = (const float*)d_in[16];
    const float* bn1g = (const float*)d_in[17];
    const float* bn1b = (const float*)d_in[18];
    const float* bn1m = (const float*)d_in[19];
    const float* bn1v = (const float*)d_in[20];
    const float* ww1  = (const float*)d_in[21];
    const float* wb1  = (const float*)d_in[22];
    const float* bn2g = (const float*)d_in[23];
    const float* bn2b = (const float*)d_in[24];
    const float* bn2m = (const float*)d_in[25];
    const float* bn2v = (const float*)d_in[26];
    const float* ww2  = (const float*)d_in[27];
    const float* wb2  = (const float*)d_in[28];

    int n = in_sizes[0] / 3;
    float* out = (float*)d_out;

    proj3_kernel<<<(n + 63) / 64, 256>>>(x, Wq, bq, Wk, bk, Wv, bv, n);
    attn_kernel<<<(n + 3) / 4, 256>>>(
        p, idx, pw1, pb1, pbng, pbnb, pbnm, pbnv, pw2, pb2,
        bn1g, bn1b, bn1m, bn1v, ww1, wb1,
        bn2g, bn2b, bn2m, bn2v, ww2, wb2,
        out, n);
}

// round 9
// speedup vs baseline: 1.1524x; 1.0740x over previous
#include <cuda_runtime.h>
#include <cuda_fp16.h>

#define NMAX 100000
#define CDIM 64
#define NSN 16

// ---- scratch (device globals; no allocation allowed) ----
__device__ float   g_xq[NMAX * CDIM];
__device__ __half2 g_kvh[NMAX * CDIM];   // packed (k, v) per (n, c); 25.6MB -> L2-resident

// ---------------------------------------------------------------------------
// Kernel 1: q -> g_xq (fp32); k,v accumulated together -> packed half2 g_kvh.
// Block = 64 rows x 64 cols, 256 threads, 4x4 register tile per thread.
// ---------------------------------------------------------------------------
__global__ __launch_bounds__(256) void proj3_kernel(
    const float* __restrict__ x,
    const float* __restrict__ Wq, const float* __restrict__ bq,
    const float* __restrict__ Wk, const float* __restrict__ bk,
    const float* __restrict__ Wv, const float* __restrict__ bv, int n)
{
    __shared__ __align__(16) float xsT[64][68];
    __shared__ __align__(16) float WT[64][68];
    __shared__ float bias[64];
    __shared__ float bias2[64];

    int t = threadIdx.x;
    int row0 = blockIdx.x * 64;

    for (int i = t; i < 64 * 64; i += 256) {
        int r = i >> 6, k = i & 63;
        int rr = row0 + r;
        xsT[k][r] = (rr < n) ? x[rr * 64 + k] : 0.f;
    }

    int tx = t & 15;
    int ty = t >> 4;

    float acc_k[4][4];
    float acc_v[4][4];

    // ---- pass 0: q ----
    __syncthreads();
    for (int i = t; i < 64 * 64; i += 256) {
        int c = i >> 6, k = i & 63;
        WT[k][c] = Wq[i];
    }
    if (t < 64) bias[t] = bq[t];
    __syncthreads();
    {
        float acc[4][4];
#pragma unroll
        for (int i = 0; i < 4; i++)
#pragma unroll
            for (int j = 0; j < 4; j++) acc[i][j] = 0.f;
#pragma unroll 8
        for (int k = 0; k < 64; k++) {
            float4 a4 = *(const float4*)&xsT[k][ty * 4];
            float4 b4 = *(const float4*)&WT[k][tx * 4];
            float a[4] = { a4.x, a4.y, a4.z, a4.w };
            float b[4] = { b4.x, b4.y, b4.z, b4.w };
#pragma unroll
            for (int i = 0; i < 4; i++)
#pragma unroll
                for (int j = 0; j < 4; j++)
                    acc[i][j] = fmaf(a[i], b[j], acc[i][j]);
        }
#pragma unroll
        for (int i = 0; i < 4; i++) {
            int r = row0 + ty * 4 + i;
            if (r < n)
#pragma unroll
                for (int j = 0; j < 4; j++) {
                    int cc = tx * 4 + j;
                    g_xq[r * 64 + cc] = acc[i][j] + bias[cc];
                }
        }
    }

    // ---- pass 1: k ----
    __syncthreads();
    for (int i = t; i < 64 * 64; i += 256) {
        int c = i >> 6, k = i & 63;
        WT[k][c] = Wk[i];
    }
    if (t < 64) { bias[t] = bk[t]; bias2[t] = bv[t]; }
    __syncthreads();
#pragma unroll
    for (int i = 0; i < 4; i++)
#pragma unroll
        for (int j = 0; j < 4; j++) acc_k[i][j] = 0.f;
#pragma unroll 8
    for (int k = 0; k < 64; k++) {
        float4 a4 = *(const float4*)&xsT[k][ty * 4];
        float4 b4 = *(const float4*)&WT[k][tx * 4];
        float a[4] = { a4.x, a4.y, a4.z, a4.w };
        float b[4] = { b4.x, b4.y, b4.z, b4.w };
#pragma unroll
        for (int i = 0; i < 4; i++)
#pragma unroll
            for (int j = 0; j < 4; j++)
                acc_k[i][j] = fmaf(a[i], b[j], acc_k[i][j]);
    }

    // ---- pass 2: v ----
    __syncthreads();
    for (int i = t; i < 64 * 64; i += 256) {
        int c = i >> 6, k = i & 63;
        WT[k][c] = Wv[i];
    }
    __syncthreads();
#pragma unroll
    for (int i = 0; i < 4; i++)
#pragma unroll
        for (int j = 0; j < 4; j++) acc_v[i][j] = 0.f;
#pragma unroll 8
    for (int k = 0; k < 64; k++) {
        float4 a4 = *(const float4*)&xsT[k][ty * 4];
        float4 b4 = *(const float4*)&WT[k][tx * 4];
        float a[4] = { a4.x, a4.y, a4.z, a4.w };
        float b[4] = { b4.x, b4.y, b4.z, b4.w };
#pragma unroll
        for (int i = 0; i < 4; i++)
#pragma unroll
            for (int j = 0; j < 4; j++)
                acc_v[i][j] = fmaf(a[i], b[j], acc_v[i][j]);
    }

    // ---- packed write: 4 half2 per i -> one STG.128, fully coalesced ----
#pragma unroll
    for (int i = 0; i < 4; i++) {
        int r = row0 + ty * 4 + i;
        if (r < n) {
            __half2 h[4];
#pragma unroll
            for (int j = 0; j < 4; j++) {
                int cc = tx * 4 + j;
                float kk = acc_k[i][j] + bias[cc];
                float vv = acc_v[i][j] + bias2[cc];
                h[j] = __floats2half2_rn(kk, vv);
            }
            *(uint4*)&g_kvh[r * 64 + tx * 4] = *(const uint4*)h;
        }
    }
}

// ---------------------------------------------------------------------------
// Kernel 2: fused attention (R6 structure). 4 points/block, 64 threads/point.
// Gather is one 4B __ldcg half2 per neighbor (1 line/warp-inst, no L1 fill).
// ---------------------------------------------------------------------------
__global__ __launch_bounds__(256, 4) void attn_kernel(
    const float* __restrict__ p, const int* __restrict__ idx,
    const float* __restrict__ pw1, const float* __restrict__ pb1,
    const float* __restrict__ pbng, const float* __restrict__ pbnb,
    const float* __restrict__ pbnm, const float* __restrict__ pbnv,
    const float* __restrict__ pw2, const float* __restrict__ pb2,
    const float* __restrict__ bn1g, const float* __restrict__ bn1b,
    const float* __restrict__ bn1m, const float* __restrict__ bn1v,
    const float* __restrict__ ww1, const float* __restrict__ wb1,
    const float* __restrict__ bn2g, const float* __restrict__ bn2b,
    const float* __restrict__ bn2m, const float* __restrict__ bn2v,
    const float* __restrict__ ww2, const float* __restrict__ wb2,
    float* __restrict__ out, int n)
{
    __shared__ __align__(16) float s_wbuf[4][16][68];  // relu(bn1(w)), stride 68
    __shared__ __align__(16) float s_u[4][16][12];     // stride 12: float4 cf-free
    __shared__ float s_lg[4][16][9];                   // stride 9
    __shared__ __align__(16) int   s_j[4][16];
    __shared__ __align__(16) float4 s_pr4[4][16];
    __shared__ __align__(16) float s_w1J[8][68];       // ww1 rows, padded 68
    __shared__ float s_pw2[64][3];
    __shared__ float s_sc1[64], s_sh1[64], s_pb2[64];
    __shared__ __align__(16) float s_w2T[8][8];
    __shared__ float s_b1[8], s_sc2[8], s_sh2[8], s_b2[8];
    __shared__ float s_pw1[9], s_pb1[3], s_psc[3], s_psh[3];

    int t = threadIdx.x;

    if (t < 64) {
        float sc = bn1g[t] * rsqrtf(bn1v[t] + 1e-5f);
        s_sc1[t] = sc;
        s_sh1[t] = bn1b[t] - bn1m[t] * sc;
        s_pb2[t] = pb2[t];
#pragma unroll
        for (int j = 0; j < 8; j++) s_w1J[j][t] = ww1[j * 64 + t];
        s_pw2[t][0] = pw2[t * 3 + 0];
        s_pw2[t][1] = pw2[t * 3 + 1];
        s_pw2[t][2] = pw2[t * 3 + 2];
    } else if (t < 72) {
        int q = t - 64;
        float sc = bn2g[q] * rsqrtf(bn2v[q] + 1e-5f);
        s_sc2[q] = sc;
        s_sh2[q] = bn2b[q] - bn2m[q] * sc;
        s_b1[q] = wb1[q];
        s_b2[q] = wb2[q];
    } else if (t >= 128 && t < 192) {
        int q = t - 128;
        int k = q >> 3, j = q & 7;
        s_w2T[k][j] = ww2[j * 8 + k];
    } else if (t >= 192 && t < 207) {
        int q = t - 192;
        if (q < 9) s_pw1[q] = pw1[q];
        else if (q < 12) s_pb1[q - 9] = pb1[q - 9];
        else {
            int k = q - 12;
            float sc = pbng[k] * rsqrtf(pbnv[k] + 1e-5f);
            s_psc[k] = sc;
            s_psh[k] = pbnb[k] - pbnm[k] * sc;
        }
    }
    __syncthreads();

    int pt = t >> 6;
    int c  = t & 63;
    int pid = blockIdx.x * 4 + pt;
    bool valid = pid < n;
    int n0 = valid ? pid : 0;

    // ---- Phase A0: 16 threads/point: idx row + p_r 3-vec ----
    if (c < 16) {
        int j = idx[n0 * 16 + c];
        s_j[pt][c] = j;
        float px = p[n0 * 3 + 0], py = p[n0 * 3 + 1], pz = p[n0 * 3 + 2];
        float dx = p[j * 3 + 0] - px;
        float dy = p[j * 3 + 1] - py;
        float dz = p[j * 3 + 2] - pz;
        float r0 = fmaf(s_pw1[0], dx, fmaf(s_pw1[1], dy, fmaf(s_pw1[2], dz, s_pb1[0])));
        float r1 = fmaf(s_pw1[3], dx, fmaf(s_pw1[4], dy, fmaf(s_pw1[5], dz, s_pb1[1])));
        float r2 = fmaf(s_pw1[6], dx, fmaf(s_pw1[7], dy, fmaf(s_pw1[8], dz, s_pb1[2])));
        float4 rr;
        rr.x = fmaxf(fmaf(r0, s_psc[0], s_psh[0]), 0.f);
        rr.y = fmaxf(fmaf(r1, s_psc[1], s_psh[1]), 0.f);
        rr.z = fmaxf(fmaf(r2, s_psc[2], s_psh[2]), 0.f);
        rr.w = 0.f;
        s_pr4[pt][c] = rr;
    }
    __syncthreads();

    float xqc = g_xq[n0 * 64 + c];
    float sc1 = s_sc1[c], sh1 = s_sh1[c];
    float w2a = s_pw2[c][0], w2b = s_pw2[c][1], w2c = s_pw2[c][2];
    float pb2c = s_pb2[c];

    // ---- Phase A1: gather packed (k,v) half2, streaming (.cg) ----
    float vpr[16];
#pragma unroll
    for (int hh = 0; hh < 2; hh++) {
        int js[8];
        {
            const int4* jp = (const int4*)&s_j[pt][hh * 8];
            int4 v0 = jp[0], v1 = jp[1];
            js[0] = v0.x; js[1] = v0.y; js[2] = v0.z; js[3] = v0.w;
            js[4] = v1.x; js[5] = v1.y; js[6] = v1.z; js[7] = v1.w;
        }
        __half2 kvh[8];
#pragma unroll
        for (int q = 0; q < 8; q++)
            kvh[q] = __ldcg(&g_kvh[js[q] * 64 + c]);
#pragma unroll
        for (int q = 0; q < 8; q++) {
            int nb = hh * 8 + q;
            float2 kv = __half22float2(kvh[q]);
            float4 rr = s_pr4[pt][nb];
            float pr = fmaf(w2a, rr.x, fmaf(w2b, rr.y, fmaf(w2c, rr.z, pb2c)));
            float w = kv.x - xqc + pr;
            s_wbuf[pt][nb][c] = fmaxf(fmaf(w, sc1, sh1), 0.f);
            vpr[nb] = kv.y + pr;
        }
    }
    __syncthreads();

    // ---- Phase B1: u = relu(bn2(wbuf @ w_w1^T + b1)). thread -> (nb, 2 j's) ----
    {
        int nb = c >> 2;
        int j0 = (c & 3) * 2;
        const float4* wrow = (const float4*)s_wbuf[pt][nb];
        const float4* w1a = (const float4*)s_w1J[j0];
        const float4* w1b = (const float4*)s_w1J[j0 + 1];
        float a0 = s_b1[j0], a1 = s_b1[j0 + 1];
#pragma unroll
        for (int k4 = 0; k4 < 16; k4++) {
            float4 wv = wrow[k4];
            float4 qa = w1a[k4];
            float4 qb = w1b[k4];
            a0 = fmaf(wv.x, qa.x, a0); a1 = fmaf(wv.x, qb.x, a1);
            a0 = fmaf(wv.y, qa.y, a0); a1 = fmaf(wv.y, qb.y, a1);
            a0 = fmaf(wv.z, qa.z, a0); a1 = fmaf(wv.z, qb.z, a1);
            a0 = fmaf(wv.w, qa.w, a0); a1 = fmaf(wv.w, qb.w, a1);
        }
        s_u[pt][nb][j0]     = fmaxf(fmaf(a0, s_sc2[j0],     s_sh2[j0]),     0.f);
        s_u[pt][nb][j0 + 1] = fmaxf(fmaf(a1, s_sc2[j0 + 1], s_sh2[j0 + 1]), 0.f);
    }
    __syncthreads();

    // ---- Phase B2: logits = u @ w_w2^T + b2 ----
    {
        int nb = c >> 2;
        int j0 = (c & 3) * 2;
        const float4* up = (const float4*)s_u[pt][nb];
        float4 u0 = up[0], u1 = up[1];
        float uu[8] = { u0.x, u0.y, u0.z, u0.w, u1.x, u1.y, u1.z, u1.w };
        float a0 = s_b2[j0], a1 = s_b2[j0 + 1];
#pragma unroll
        for (int k = 0; k < 8; k++) {
            float2 qv = *(const float2*)&s_w2T[k][j0];
            a0 = fmaf(uu[k], qv.x, a0);
            a1 = fmaf(uu[k], qv.y, a1);
        }
        s_lg[pt][nb][j0] = a0;
        s_lg[pt][nb][j0 + 1] = a1;
    }
    __syncthreads();

    // ---- Phase C: softmax over neighbors ----
    if (c < 8) {
        int j = c;
        float m = -1e30f;
#pragma unroll
        for (int nb = 0; nb < 16; nb++) m = fmaxf(m, s_lg[pt][nb][j]);
        float e[16];
        float sum = 0.f;
#pragma unroll
        for (int nb = 0; nb < 16; nb++) {
            e[nb] = __expf(s_lg[pt][nb][j] - m);
            sum += e[nb];
        }
        float inv = 1.f / sum;
#pragma unroll
        for (int nb = 0; nb < 16; nb++) s_lg[pt][nb][j] = e[nb] * inv;
    }
    __syncthreads();

    // ---- Phase D: out[c] = sum_nb vpr[nb] * w[nb][c%8] ----
    if (valid) {
        int j = c & 7;
        float acc = 0.f;
#pragma unroll
        for (int nb = 0; nb < 16; nb++)
            acc = fmaf(vpr[nb], s_lg[pt][nb][j], acc);
        out[pid * 64 + c] = acc;
    }
}

// ---------------------------------------------------------------------------
extern "C" void kernel_launch(void* const* d_in, const int* in_sizes, int n_in,
                              void* d_out, int out_size)
{
    const float* p    = (const float*)d_in[0];
    const float* x    = (const float*)d_in[1];
    const int*   idx  = (const int*)d_in[2];
    const float* Wq   = (const float*)d_in[3];
    const float* bq   = (const float*)d_in[4];
    const float* Wk   = (const float*)d_in[5];
    const float* bk   = (const float*)d_in[6];
    const float* Wv   = (const float*)d_in[7];
    const float* bv   = (const float*)d_in[8];
    const float* pw1  = (const float*)d_in[9];
    const float* pb1  = (const float*)d_in[10];
    const float* pbng = (const float*)d_in[11];
    const float* pbnb = (const float*)d_in[12];
    const float* pbnm = (const float*)d_in[13];
    const float* pbnv = (const float*)d_in[14];
    const float* pw2  = (const float*)d_in[15];
    const float* pb2  = (const float*)d_in[16];
    const float* bn1g = (const float*)d_in[17];
    const float* bn1b = (const float*)d_in[18];
    const float* bn1m = (const float*)d_in[19];
    const float* bn1v = (const float*)d_in[20];
    const float* ww1  = (const float*)d_in[21];
    const float* wb1  = (const float*)d_in[22];
    const float* bn2g = (const float*)d_in[23];
    const float* bn2b = (const float*)d_in[24];
    const float* bn2m = (const float*)d_in[25];
    const float* bn2v = (const float*)d_in[26];
    const float* ww2  = (const float*)d_in[27];
    const float* wb2  = (const float*)d_in[28];

    int n = in_sizes[0] / 3;
    float* out = (float*)d_out;

    proj3_kernel<<<(n + 63) / 64, 256>>>(x, Wq, bq, Wk, bk, Wv, bv, n);
    attn_kernel<<<(n + 3) / 4, 256>>>(
        p, idx, pw1, pb1, pbng, pbnb, pbnm, pbnv, pw2, pb2,
        bn1g, bn1b, bn1m, bn1v, ww1, wb1,
        bn2g, bn2b, bn2m, bn2v, ww2, wb2,
        out, n);
}

// round 10
// speedup vs baseline: 1.2540x; 1.0882x over previous
#include <cuda_runtime.h>
#include <cuda_fp16.h>

#define NMAX 100000
#define CDIM 64
#define NSN 16

// ---- scratch (device globals; no allocation allowed) ----
__device__ float   g_xq[NMAX * CDIM];
__device__ __half2 g_kvh[NMAX * CDIM];   // packed (k, v) per (n, c); 25.6MB -> L2-resident

// ---------------------------------------------------------------------------
// Kernel 1 (fused): q,k,v in ONE k-loop. xsT + 3 W^T tiles in dynamic smem.
// 48 FMA per 4 LDS.128 -> FMA-pipe bound. q -> fp32 g_xq; (k,v) -> half2 g_kvh.
// ---------------------------------------------------------------------------
__global__ __launch_bounds__(256, 3) void proj3_kernel(
    const float* __restrict__ x,
    const float* __restrict__ Wq, const float* __restrict__ bq,
    const float* __restrict__ Wk, const float* __restrict__ bk,
    const float* __restrict__ Wv, const float* __restrict__ bv, int n)
{
    extern __shared__ float sm[];
    float (*xsT)[68] = reinterpret_cast<float(*)[68]>(sm);            // 64x68
    float (*WTq)[68] = reinterpret_cast<float(*)[68]>(sm + 4352);
    float (*WTk)[68] = reinterpret_cast<float(*)[68]>(sm + 8704);
    float (*WTv)[68] = reinterpret_cast<float(*)[68]>(sm + 13056);
    float* biasq = sm + 17408;
    float* biask = biasq + 64;
    float* biasv = biask + 64;

    int t = threadIdx.x;
    int row0 = blockIdx.x * 64;

    for (int i = t; i < 64 * 64; i += 256) {
        int r = i >> 6, k = i & 63;
        int rr = row0 + r;
        xsT[k][r] = (rr < n) ? x[rr * 64 + k] : 0.f;   // coalesced global read
    }
    for (int i = t; i < 64 * 64; i += 256) {
        int c = i >> 6, k = i & 63;
        WTq[k][c] = Wq[i];
        WTk[k][c] = Wk[i];
        WTv[k][c] = Wv[i];
    }
    if (t < 64) { biasq[t] = bq[t]; biask[t] = bk[t]; biasv[t] = bv[t]; }
    __syncthreads();

    int tx = t & 15;   // col group (4 cols)
    int ty = t >> 4;   // row group (4 rows)

    float aq[4][4], ak[4][4], av[4][4];
#pragma unroll
    for (int i = 0; i < 4; i++)
#pragma unroll
        for (int j = 0; j < 4; j++) { aq[i][j] = 0.f; ak[i][j] = 0.f; av[i][j] = 0.f; }

#pragma unroll 4
    for (int k = 0; k < 64; k++) {
        float4 a4 = *(const float4*)&xsT[k][ty * 4];
        float4 q4 = *(const float4*)&WTq[k][tx * 4];
        float4 k4 = *(const float4*)&WTk[k][tx * 4];
        float4 v4 = *(const float4*)&WTv[k][tx * 4];
        float a[4] = { a4.x, a4.y, a4.z, a4.w };
        float qb[4] = { q4.x, q4.y, q4.z, q4.w };
        float kb[4] = { k4.x, k4.y, k4.z, k4.w };
        float vb[4] = { v4.x, v4.y, v4.z, v4.w };
#pragma unroll
        for (int i = 0; i < 4; i++)
#pragma unroll
            for (int j = 0; j < 4; j++) {
                aq[i][j] = fmaf(a[i], qb[j], aq[i][j]);
                ak[i][j] = fmaf(a[i], kb[j], ak[i][j]);
                av[i][j] = fmaf(a[i], vb[j], av[i][j]);
            }
    }

#pragma unroll
    for (int i = 0; i < 4; i++) {
        int r = row0 + ty * 4 + i;
        if (r < n) {
            int c0 = tx * 4;
            float4 qo;
            qo.x = aq[i][0] + biasq[c0 + 0];
            qo.y = aq[i][1] + biasq[c0 + 1];
            qo.z = aq[i][2] + biasq[c0 + 2];
            qo.w = aq[i][3] + biasq[c0 + 3];
            *(float4*)&g_xq[r * 64 + c0] = qo;
            __half2 h[4];
#pragma unroll
            for (int j = 0; j < 4; j++) {
                float kk = ak[i][j] + biask[c0 + j];
                float vv = av[i][j] + biasv[c0 + j];
                h[j] = __floats2half2_rn(kk, vv);
            }
            *(uint4*)&g_kvh[r * 64 + c0] = *(const uint4*)h;
        }
    }
}

// ---------------------------------------------------------------------------
// Kernel 2: fused attention. 4 points/block, 64 threads/point.
// half2 kv gather (.cg); transposed logits buffer for vectorized softmax/D.
// ---------------------------------------------------------------------------
__global__ __launch_bounds__(256, 4) void attn_kernel(
    const float* __restrict__ p, const int* __restrict__ idx,
    const float* __restrict__ pw1, const float* __restrict__ pb1,
    const float* __restrict__ pbng, const float* __restrict__ pbnb,
    const float* __restrict__ pbnm, const float* __restrict__ pbnv,
    const float* __restrict__ pw2, const float* __restrict__ pb2,
    const float* __restrict__ bn1g, const float* __restrict__ bn1b,
    const float* __restrict__ bn1m, const float* __restrict__ bn1v,
    const float* __restrict__ ww1, const float* __restrict__ wb1,
    const float* __restrict__ bn2g, const float* __restrict__ bn2b,
    const float* __restrict__ bn2m, const float* __restrict__ bn2v,
    const float* __restrict__ ww2, const float* __restrict__ wb2,
    float* __restrict__ out, int n)
{
    __shared__ __align__(16) float s_wbuf[4][16][68];  // relu(bn1(w)), stride 68
    __shared__ __align__(16) float s_u[4][16][12];     // stride 12: float4 cf-free
    __shared__ __align__(16) float s_lg2[4][8][20];    // logits TRANSPOSED [j][nb]
    __shared__ __align__(16) int   s_j[4][16];
    __shared__ __align__(16) float4 s_pr4[4][16];
    __shared__ __align__(16) float s_w1J[8][68];       // ww1 rows, padded 68
    __shared__ float s_pw2[64][3];
    __shared__ float s_sc1[64], s_sh1[64], s_pb2[64];
    __shared__ __align__(16) float s_w2T[8][8];
    __shared__ float s_b1[8], s_sc2[8], s_sh2[8], s_b2[8];
    __shared__ float s_pw1[9], s_pb1[3], s_psc[3], s_psh[3];

    int t = threadIdx.x;

    if (t < 64) {
        float sc = bn1g[t] * rsqrtf(bn1v[t] + 1e-5f);
        s_sc1[t] = sc;
        s_sh1[t] = bn1b[t] - bn1m[t] * sc;
        s_pb2[t] = pb2[t];
#pragma unroll
        for (int j = 0; j < 8; j++) s_w1J[j][t] = ww1[j * 64 + t];
        s_pw2[t][0] = pw2[t * 3 + 0];
        s_pw2[t][1] = pw2[t * 3 + 1];
        s_pw2[t][2] = pw2[t * 3 + 2];
    } else if (t < 72) {
        int q = t - 64;
        float sc = bn2g[q] * rsqrtf(bn2v[q] + 1e-5f);
        s_sc2[q] = sc;
        s_sh2[q] = bn2b[q] - bn2m[q] * sc;
        s_b1[q] = wb1[q];
        s_b2[q] = wb2[q];
    } else if (t >= 128 && t < 192) {
        int q = t - 128;
        int k = q >> 3, j = q & 7;
        s_w2T[k][j] = ww2[j * 8 + k];
    } else if (t >= 192 && t < 207) {
        int q = t - 192;
        if (q < 9) s_pw1[q] = pw1[q];
        else if (q < 12) s_pb1[q - 9] = pb1[q - 9];
        else {
            int k = q - 12;
            float sc = pbng[k] * rsqrtf(pbnv[k] + 1e-5f);
            s_psc[k] = sc;
            s_psh[k] = pbnb[k] - pbnm[k] * sc;
        }
    }
    __syncthreads();

    int pt = t >> 6;
    int c  = t & 63;
    int pid = blockIdx.x * 4 + pt;
    bool valid = pid < n;
    int n0 = valid ? pid : 0;

    // ---- Phase A0: 16 threads/point: idx row + p_r 3-vec ----
    if (c < 16) {
        int j = idx[n0 * 16 + c];
        s_j[pt][c] = j;
        float px = p[n0 * 3 + 0], py = p[n0 * 3 + 1], pz = p[n0 * 3 + 2];
        float dx = p[j * 3 + 0] - px;
        float dy = p[j * 3 + 1] - py;
        float dz = p[j * 3 + 2] - pz;
        float r0 = fmaf(s_pw1[0], dx, fmaf(s_pw1[1], dy, fmaf(s_pw1[2], dz, s_pb1[0])));
        float r1 = fmaf(s_pw1[3], dx, fmaf(s_pw1[4], dy, fmaf(s_pw1[5], dz, s_pb1[1])));
        float r2 = fmaf(s_pw1[6], dx, fmaf(s_pw1[7], dy, fmaf(s_pw1[8], dz, s_pb1[2])));
        float4 rr;
        rr.x = fmaxf(fmaf(r0, s_psc[0], s_psh[0]), 0.f);
        rr.y = fmaxf(fmaf(r1, s_psc[1], s_psh[1]), 0.f);
        rr.z = fmaxf(fmaf(r2, s_psc[2], s_psh[2]), 0.f);
        rr.w = 0.f;
        s_pr4[pt][c] = rr;
    }
    __syncthreads();

    float xqc = g_xq[n0 * 64 + c];
    float sc1 = s_sc1[c], sh1 = s_sh1[c];
    float w2a = s_pw2[c][0], w2b = s_pw2[c][1], w2c = s_pw2[c][2];
    float pb2c = s_pb2[c];

    // ---- Phase A1: gather packed (k,v) half2, streaming (.cg) ----
    float vpr[16];
#pragma unroll
    for (int hh = 0; hh < 2; hh++) {
        int js[8];
        {
            const int4* jp = (const int4*)&s_j[pt][hh * 8];
            int4 v0 = jp[0], v1 = jp[1];
            js[0] = v0.x; js[1] = v0.y; js[2] = v0.z; js[3] = v0.w;
            js[4] = v1.x; js[5] = v1.y; js[6] = v1.z; js[7] = v1.w;
        }
        __half2 kvh[8];
#pragma unroll
        for (int q = 0; q < 8; q++)
            kvh[q] = __ldcg(&g_kvh[js[q] * 64 + c]);
#pragma unroll
        for (int q = 0; q < 8; q++) {
            int nb = hh * 8 + q;
            float2 kv = __half22float2(kvh[q]);
            float4 rr = s_pr4[pt][nb];
            float pr = fmaf(w2a, rr.x, fmaf(w2b, rr.y, fmaf(w2c, rr.z, pb2c)));
            float w = kv.x - xqc + pr;
            s_wbuf[pt][nb][c] = fmaxf(fmaf(w, sc1, sh1), 0.f);
            vpr[nb] = kv.y + pr;
        }
    }
    __syncthreads();

    // ---- Phase B1: u = relu(bn2(wbuf @ w_w1^T + b1)). thread -> (nb, 2 j's) ----
    {
        int nb = c >> 2;
        int j0 = (c & 3) * 2;
        const float4* wrow = (const float4*)s_wbuf[pt][nb];
        const float4* w1a = (const float4*)s_w1J[j0];
        const float4* w1b = (const float4*)s_w1J[j0 + 1];
        float a0 = s_b1[j0], a1 = s_b1[j0 + 1];
#pragma unroll
        for (int k4 = 0; k4 < 16; k4++) {
            float4 wv = wrow[k4];
            float4 qa = w1a[k4];
            float4 qb = w1b[k4];
            a0 = fmaf(wv.x, qa.x, a0); a1 = fmaf(wv.x, qb.x, a1);
            a0 = fmaf(wv.y, qa.y, a0); a1 = fmaf(wv.y, qb.y, a1);
            a0 = fmaf(wv.z, qa.z, a0); a1 = fmaf(wv.z, qb.z, a1);
            a0 = fmaf(wv.w, qa.w, a0); a1 = fmaf(wv.w, qb.w, a1);
        }
        s_u[pt][nb][j0]     = fmaxf(fmaf(a0, s_sc2[j0],     s_sh2[j0]),     0.f);
        s_u[pt][nb][j0 + 1] = fmaxf(fmaf(a1, s_sc2[j0 + 1], s_sh2[j0 + 1]), 0.f);
    }
    __syncthreads();

    // ---- Phase B2: logits = u @ w_w2^T + b2 (written TRANSPOSED [j][nb]) ----
    {
        int nb = c >> 2;
        int j0 = (c & 3) * 2;
        const float4* up = (const float4*)s_u[pt][nb];
        float4 u0 = up[0], u1 = up[1];
        float uu[8] = { u0.x, u0.y, u0.z, u0.w, u1.x, u1.y, u1.z, u1.w };
        float a0 = s_b2[j0], a1 = s_b2[j0 + 1];
#pragma unroll
        for (int k = 0; k < 8; k++) {
            float2 qv = *(const float2*)&s_w2T[k][j0];
            a0 = fmaf(uu[k], qv.x, a0);
            a1 = fmaf(uu[k], qv.y, a1);
        }
        s_lg2[pt][j0][nb]     = a0;
        s_lg2[pt][j0 + 1][nb] = a1;
    }
    __syncthreads();

    // ---- Phase C: softmax over neighbors (vectorized row access) ----
    if (c < 8) {
        int j = c;
        float4 L[4];
#pragma unroll
        for (int q = 0; q < 4; q++) L[q] = *(const float4*)&s_lg2[pt][j][q * 4];
        float lv[16] = { L[0].x, L[0].y, L[0].z, L[0].w,
                         L[1].x, L[1].y, L[1].z, L[1].w,
                         L[2].x, L[2].y, L[2].z, L[2].w,
                         L[3].x, L[3].y, L[3].z, L[3].w };
        float m = -1e30f;
#pragma unroll
        for (int nb = 0; nb < 16; nb++) m = fmaxf(m, lv[nb]);
        float sum = 0.f;
#pragma unroll
        for (int nb = 0; nb < 16; nb++) {
            lv[nb] = __expf(lv[nb] - m);
            sum += lv[nb];
        }
        float inv = 1.f / sum;
#pragma unroll
        for (int q = 0; q < 4; q++) {
            float4 o;
            o.x = lv[q * 4 + 0] * inv;
            o.y = lv[q * 4 + 1] * inv;
            o.z = lv[q * 4 + 2] * inv;
            o.w = lv[q * 4 + 3] * inv;
            *(float4*)&s_lg2[pt][j][q * 4] = o;
        }
    }
    __syncthreads();

    // ---- Phase D: out[c] = sum_nb vpr[nb] * w[j=c%8][nb] (float4 row reads) ----
    if (valid) {
        int j = c & 7;
        float acc = 0.f;
#pragma unroll
        for (int q = 0; q < 4; q++) {
            float4 w4 = *(const float4*)&s_lg2[pt][j][q * 4];
            acc = fmaf(vpr[q * 4 + 0], w4.x, acc);
            acc = fmaf(vpr[q * 4 + 1], w4.y, acc);
            acc = fmaf(vpr[q * 4 + 2], w4.z, acc);
            acc = fmaf(vpr[q * 4 + 3], w4.w, acc);
        }
        out[pid * 64 + c] = acc;
    }
}

// ---------------------------------------------------------------------------
extern "C" void kernel_launch(void* const* d_in, const int* in_sizes, int n_in,
                              void* d_out, int out_size)
{
    const float* p    = (const float*)d_in[0];
    const float* x    = (const float*)d_in[1];
    const int*   idx  = (const int*)d_in[2];
    const float* Wq   = (const float*)d_in[3];
    const float* bq   = (const float*)d_in[4];
    const float* Wk   = (const float*)d_in[5];
    const float* bk   = (const float*)d_in[6];
    const float* Wv   = (const float*)d_in[7];
    const float* bv   = (const float*)d_in[8];
    const float* pw1  = (const float*)d_in[9];
    const float* pb1  = (const float*)d_in[10];
    const float* pbng = (const float*)d_in[11];
    const float* pbnb = (const float*)d_in[12];
    const float* pbnm = (const float*)d_in[13];
    const float* pbnv = (const float*)d_in[14];
    const float* pw2  = (const float*)d_in[15];
    const float* pb2  = (const float*)d_in[16];
    const float* bn1g = (const float*)d_in[17];
    const float* bn1b = (const float*)d_in[18];
    const float* bn1m = (const float*)d_in[19];
    const float* bn1v = (const float*)d_in[20];
    const float* ww1  = (const float*)d_in[21];
    const float* wb1  = (const float*)d_in[22];
    const float* bn2g = (const float*)d_in[23];
    const float* bn2b = (const float*)d_in[24];
    const float* bn2m = (const float*)d_in[25];
    const float* bn2v = (const float*)d_in[26];
    const float* ww2  = (const float*)d_in[27];
    const float* wb2  = (const float*)d_in[28];

    int n = in_sizes[0] / 3;
    float* out = (float*)d_out;

    const int PROJ_SMEM = 70400;
    cudaFuncSetAttribute(proj3_kernel,
                         cudaFuncAttributeMaxDynamicSharedMemorySize, PROJ_SMEM);

    proj3_kernel<<<(n + 63) / 64, 256, PROJ_SMEM>>>(x, Wq, bq, Wk, bk, Wv, bv, n);
    attn_kernel<<<(n + 3) / 4, 256>>>(
        p, idx, pw1, pb1, pbng, pbnb, pbnm, pbnv, pw2, pb2,
        bn1g, bn1b, bn1m, bn1v, ww1, wb1,
        bn2g, bn2b, bn2m, bn2v, ww2, wb2,
        out, n);
}

// round 12
// speedup vs baseline: 1.5153x; 1.2083x over previous
#include <cuda_runtime.h>
#include <cuda_fp16.h>
#include <cstdint>

#define NMAX 100000
#define CDIM 64
#define NSN 16

// ---- scratch (device globals; no allocation allowed) ----
__device__ float   g_xq[NMAX * CDIM];
__device__ __half2 g_kvh[NMAX * CDIM];   // packed (k, v) per (n, c); 25.6MB -> L2-resident

// ---------------------------------------------------------------------------
// Kernel 1 (fused): q,k,v in ONE k-loop. xsT + 3 W^T tiles in dynamic smem.
// ---------------------------------------------------------------------------
__global__ __launch_bounds__(256, 3) void proj3_kernel(
    const float* __restrict__ x,
    const float* __restrict__ Wq, const float* __restrict__ bq,
    const float* __restrict__ Wk, const float* __restrict__ bk,
    const float* __restrict__ Wv, const float* __restrict__ bv, int n)
{
    extern __shared__ float sm[];
    float (*xsT)[68] = reinterpret_cast<float(*)[68]>(sm);            // 64x68
    float (*WTq)[68] = reinterpret_cast<float(*)[68]>(sm + 4352);
    float (*WTk)[68] = reinterpret_cast<float(*)[68]>(sm + 8704);
    float (*WTv)[68] = reinterpret_cast<float(*)[68]>(sm + 13056);
    float* biasq = sm + 17408;
    float* biask = biasq + 64;
    float* biasv = biask + 64;

    int t = threadIdx.x;
    int row0 = blockIdx.x * 64;

    for (int i = t; i < 64 * 64; i += 256) {
        int r = i >> 6, k = i & 63;
        int rr = row0 + r;
        xsT[k][r] = (rr < n) ? x[rr * 64 + k] : 0.f;
    }
    for (int i = t; i < 64 * 64; i += 256) {
        int c = i >> 6, k = i & 63;
        WTq[k][c] = Wq[i];
        WTk[k][c] = Wk[i];
        WTv[k][c] = Wv[i];
    }
    if (t < 64) { biasq[t] = bq[t]; biask[t] = bk[t]; biasv[t] = bv[t]; }
    __syncthreads();

    int tx = t & 15;
    int ty = t >> 4;

    float aq[4][4], ak[4][4], av[4][4];
#pragma unroll
    for (int i = 0; i < 4; i++)
#pragma unroll
        for (int j = 0; j < 4; j++) { aq[i][j] = 0.f; ak[i][j] = 0.f; av[i][j] = 0.f; }

#pragma unroll 4
    for (int k = 0; k < 64; k++) {
        float4 a4 = *(const float4*)&xsT[k][ty * 4];
        float4 q4 = *(const float4*)&WTq[k][tx * 4];
        float4 k4 = *(const float4*)&WTk[k][tx * 4];
        float4 v4 = *(const float4*)&WTv[k][tx * 4];
        float a[4] = { a4.x, a4.y, a4.z, a4.w };
        float qb[4] = { q4.x, q4.y, q4.z, q4.w };
        float kb[4] = { k4.x, k4.y, k4.z, k4.w };
        float vb[4] = { v4.x, v4.y, v4.z, v4.w };
#pragma unroll
        for (int i = 0; i < 4; i++)
#pragma unroll
            for (int j = 0; j < 4; j++) {
                aq[i][j] = fmaf(a[i], qb[j], aq[i][j]);
                ak[i][j] = fmaf(a[i], kb[j], ak[i][j]);
                av[i][j] = fmaf(a[i], vb[j], av[i][j]);
            }
    }

#pragma unroll
    for (int i = 0; i < 4; i++) {
        int r = row0 + ty * 4 + i;
        if (r < n) {
            int c0 = tx * 4;
            float4 qo;
            qo.x = aq[i][0] + biasq[c0 + 0];
            qo.y = aq[i][1] + biasq[c0 + 1];
            qo.z = aq[i][2] + biasq[c0 + 2];
            qo.w = aq[i][3] + biasq[c0 + 3];
            *(float4*)&g_xq[r * 64 + c0] = qo;
            __half2 h[4];
#pragma unroll
            for (int j = 0; j < 4; j++) {
                float kk = ak[i][j] + biask[c0 + j];
                float vv = av[i][j] + biasv[c0 + j];
                h[j] = __floats2half2_rn(kk, vv);
            }
            *(uint4*)&g_kvh[r * 64 + c0] = *(const uint4*)h;
        }
    }
}

// ---------------------------------------------------------------------------
// Kernel 2: fused attention. 4 points/block, 64 threads/point.
// B1 done as one 64x8x64 fp16 GEMM via mma.sync.m16n8k16 (warp w = point w).
// ---------------------------------------------------------------------------
__global__ __launch_bounds__(256, 4) void attn_kernel(
    const float* __restrict__ p, const int* __restrict__ idx,
    const float* __restrict__ pw1, const float* __restrict__ pb1,
    const float* __restrict__ pbng, const float* __restrict__ pbnb,
    const float* __restrict__ pbnm, const float* __restrict__ pbnv,
    const float* __restrict__ pw2, const float* __restrict__ pb2,
    const float* __restrict__ bn1g, const float* __restrict__ bn1b,
    const float* __restrict__ bn1m, const float* __restrict__ bn1v,
    const float* __restrict__ ww1, const float* __restrict__ wb1,
    const float* __restrict__ bn2g, const float* __restrict__ bn2b,
    const float* __restrict__ bn2m, const float* __restrict__ bn2v,
    const float* __restrict__ ww2, const float* __restrict__ wb2,
    float* __restrict__ out, int n)
{
    __shared__ __align__(16) __half s_wA[64 * 72];     // wbuf fp16: row=pt*16+nb, 64 ch, stride 72
    __shared__ __align__(16) __half s_w1h[8 * 72];     // w1 fp16: row=j, 64 ch, stride 72
    __shared__ __align__(16) float s_u[4][16][12];     // post-bn2 u, stride 12
    __shared__ __align__(16) float s_lg2[4][8][20];    // logits TRANSPOSED [j][nb]
    __shared__ __align__(16) int   s_j[4][16];
    __shared__ __align__(16) float4 s_pr4[4][16];
    __shared__ float s_pw2[64][3];
    __shared__ float s_sc1[64], s_sh1[64], s_pb2[64];
    __shared__ __align__(16) float s_w2T[8][8];
    __shared__ float s_b1[8], s_sc2[8], s_sh2[8], s_b2[8];
    __shared__ float s_pw1[9], s_pb1[3], s_psc[3], s_psh[3];

    int t = threadIdx.x;

    if (t < 64) {
        float sc = bn1g[t] * rsqrtf(bn1v[t] + 1e-5f);
        s_sc1[t] = sc;
        s_sh1[t] = bn1b[t] - bn1m[t] * sc;
        s_pb2[t] = pb2[t];
#pragma unroll
        for (int j = 0; j < 8; j++) s_w1h[j * 72 + t] = __float2half(ww1[j * 64 + t]);
        s_pw2[t][0] = pw2[t * 3 + 0];
        s_pw2[t][1] = pw2[t * 3 + 1];
        s_pw2[t][2] = pw2[t * 3 + 2];
    } else if (t < 72) {
        int q = t - 64;
        float sc = bn2g[q] * rsqrtf(bn2v[q] + 1e-5f);
        s_sc2[q] = sc;
        s_sh2[q] = bn2b[q] - bn2m[q] * sc;
        s_b1[q] = wb1[q];
        s_b2[q] = wb2[q];
    } else if (t >= 128 && t < 192) {
        int q = t - 128;
        int k = q >> 3, j = q & 7;
        s_w2T[k][j] = ww2[j * 8 + k];
    } else if (t >= 192 && t < 207) {
        int q = t - 192;
        if (q < 9) s_pw1[q] = pw1[q];
        else if (q < 12) s_pb1[q - 9] = pb1[q - 9];
        else {
            int k = q - 12;
            float sc = pbng[k] * rsqrtf(pbnv[k] + 1e-5f);
            s_psc[k] = sc;
            s_psh[k] = pbnb[k] - pbnm[k] * sc;
        }
    }
    __syncthreads();

    int pt = t >> 6;
    int c  = t & 63;
    int l  = t & 31;
    int pid = blockIdx.x * 4 + pt;
    bool valid = pid < n;
    int n0 = valid ? pid : 0;

    // ---- Phase A0: 16 threads/point: idx row + p_r 3-vec ----
    if (c < 16) {
        int j = idx[n0 * 16 + c];
        s_j[pt][c] = j;
        float px = p[n0 * 3 + 0], py = p[n0 * 3 + 1], pz = p[n0 * 3 + 2];
        float dx = p[j * 3 + 0] - px;
        float dy = p[j * 3 + 1] - py;
        float dz = p[j * 3 + 2] - pz;
        float r0 = fmaf(s_pw1[0], dx, fmaf(s_pw1[1], dy, fmaf(s_pw1[2], dz, s_pb1[0])));
        float r1 = fmaf(s_pw1[3], dx, fmaf(s_pw1[4], dy, fmaf(s_pw1[5], dz, s_pb1[1])));
        float r2 = fmaf(s_pw1[6], dx, fmaf(s_pw1[7], dy, fmaf(s_pw1[8], dz, s_pb1[2])));
        float4 rr;
        rr.x = fmaxf(fmaf(r0, s_psc[0], s_psh[0]), 0.f);
        rr.y = fmaxf(fmaf(r1, s_psc[1], s_psh[1]), 0.f);
        rr.z = fmaxf(fmaf(r2, s_psc[2], s_psh[2]), 0.f);
        rr.w = 0.f;
        s_pr4[pt][c] = rr;
    }
    __syncthreads();

    float xqc = g_xq[n0 * 64 + c];
    float sc1 = s_sc1[c], sh1 = s_sh1[c];
    float w2a = s_pw2[c][0], w2b = s_pw2[c][1], w2c = s_pw2[c][2];
    float pb2c = s_pb2[c];

    // ---- Phase A1: gather packed (k,v) half2; wbuf -> fp16 smem rows ----
    float vpr[16];
#pragma unroll
    for (int hh = 0; hh < 2; hh++) {
        int js[8];
        {
            const int4* jp = (const int4*)&s_j[pt][hh * 8];
            int4 v0 = jp[0], v1 = jp[1];
            js[0] = v0.x; js[1] = v0.y; js[2] = v0.z; js[3] = v0.w;
            js[4] = v1.x; js[5] = v1.y; js[6] = v1.z; js[7] = v1.w;
        }
        __half2 kvh[8];
#pragma unroll
        for (int q = 0; q < 8; q++)
            kvh[q] = __ldcg(&g_kvh[js[q] * 64 + c]);
#pragma unroll
        for (int q = 0; q < 8; q++) {
            int nb = hh * 8 + q;
            float2 kv = __half22float2(kvh[q]);
            float4 rr = s_pr4[pt][nb];
            float pr = fmaf(w2a, rr.x, fmaf(w2b, rr.y, fmaf(w2c, rr.z, pb2c)));
            float w = kv.x - xqc + pr;
            s_wA[(pt * 16 + nb) * 72 + c] =
                __float2half(fmaxf(fmaf(w, sc1, sh1), 0.f));
            vpr[nb] = kv.y + pr;
        }
    }
    __syncthreads();

    // ---- Phase B1: 64x8x64 GEMM via mma.sync. Warp w handles point w. ----
    {
        int wid = t >> 5;
        if (wid < 4) {
            int g  = l >> 2;          // 0..7
            int tt = l & 3;           // 0..3
            float c0 = 0.f, c1 = 0.f, c2 = 0.f, c3 = 0.f;
            const __half* Ab  = &s_wA[(wid * 16 + g) * 72];
            const __half* Ab8 = Ab + 8 * 72;
            const __half* Bb  = &s_w1h[g * 72];
#pragma unroll
            for (int ks = 0; ks < 4; ks++) {
                int k0 = ks * 16 + 2 * tt;
                unsigned int a0 = *(const unsigned int*)&Ab [k0];
                unsigned int a1 = *(const unsigned int*)&Ab8[k0];
                unsigned int a2 = *(const unsigned int*)&Ab [k0 + 8];
                unsigned int a3 = *(const unsigned int*)&Ab8[k0 + 8];
                unsigned int b0 = *(const unsigned int*)&Bb [k0];
                unsigned int b1 = *(const unsigned int*)&Bb [k0 + 8];
                asm volatile(
                    "mma.sync.aligned.m16n8k16.row.col.f32.f16.f16.f32 "
                    "{%0,%1,%2,%3}, {%4,%5,%6,%7}, {%8,%9}, {%0,%1,%2,%3};"
                    : "+f"(c0), "+f"(c1), "+f"(c2), "+f"(c3)
                    : "r"(a0), "r"(a1), "r"(a2), "r"(a3), "r"(b0), "r"(b1));
            }
            int j0 = 2 * tt;
            float b10 = s_b1[j0],  b11 = s_b1[j0 + 1];
            float s20 = s_sc2[j0], s21 = s_sc2[j0 + 1];
            float h20 = s_sh2[j0], h21 = s_sh2[j0 + 1];
            s_u[wid][g][j0]         = fmaxf(fmaf(c0 + b10, s20, h20), 0.f);
            s_u[wid][g][j0 + 1]     = fmaxf(fmaf(c1 + b11, s21, h21), 0.f);
            s_u[wid][g + 8][j0]     = fmaxf(fmaf(c2 + b10, s20, h20), 0.f);
            s_u[wid][g + 8][j0 + 1] = fmaxf(fmaf(c3 + b11, s21, h21), 0.f);
        }
    }
    __syncthreads();

    // ---- Phase B2: logits = u @ w_w2^T + b2 (written TRANSPOSED [j][nb]) ----
    {
        int nb = c >> 2;
        int j0 = (c & 3) * 2;
        const float4* up = (const float4*)s_u[pt][nb];
        float4 u0 = up[0], u1 = up[1];
        float uu[8] = { u0.x, u0.y, u0.z, u0.w, u1.x, u1.y, u1.z, u1.w };
        float a0 = s_b2[j0], a1 = s_b2[j0 + 1];
#pragma unroll
        for (int k = 0; k < 8; k++) {
            float2 qv = *(const float2*)&s_w2T[k][j0];
            a0 = fmaf(uu[k], qv.x, a0);
            a1 = fmaf(uu[k], qv.y, a1);
        }
        s_lg2[pt][j0][nb]     = a0;
        s_lg2[pt][j0 + 1][nb] = a1;
    }
    __syncthreads();

    // ---- Phase C: softmax over neighbors (vectorized row access) ----
    if (c < 8) {
        int j = c;
        float4 L[4];
#pragma unroll
        for (int q = 0; q < 4; q++) L[q] = *(const float4*)&s_lg2[pt][j][q * 4];
        float lv[16] = { L[0].x, L[0].y, L[0].z, L[0].w,
                         L[1].x, L[1].y, L[1].z, L[1].w,
                         L[2].x, L[2].y, L[2].z, L[2].w,
                         L[3].x, L[3].y, L[3].z, L[3].w };
        float m = -1e30f;
#pragma unroll
        for (int nb = 0; nb < 16; nb++) m = fmaxf(m, lv[nb]);
        float sum = 0.f;
#pragma unroll
        for (int nb = 0; nb < 16; nb++) {
            lv[nb] = __expf(lv[nb] - m);
            sum += lv[nb];
        }
        float inv = 1.f / sum;
#pragma unroll
        for (int q = 0; q < 4; q++) {
            float4 o;
            o.x = lv[q * 4 + 0] * inv;
            o.y = lv[q * 4 + 1] * inv;
            o.z = lv[q * 4 + 2] * inv;
            o.w = lv[q * 4 + 3] * inv;
            *(float4*)&s_lg2[pt][j][q * 4] = o;
        }
    }
    __syncthreads();

    // ---- Phase D: out[c] = sum_nb vpr[nb] * w[j=c%8][nb] (float4 row reads) ----
    if (valid) {
        int j = c & 7;
        float acc = 0.f;
#pragma unroll
        for (int q = 0; q < 4; q++) {
            float4 w4 = *(const float4*)&s_lg2[pt][j][q * 4];
            acc = fmaf(vpr[q * 4 + 0], w4.x, acc);
            acc = fmaf(vpr[q * 4 + 1], w4.y, acc);
            acc = fmaf(vpr[q * 4 + 2], w4.z, acc);
            acc = fmaf(vpr[q * 4 + 3], w4.w, acc);
        }
        out[pid * 64 + c] = acc;
    }
}

// ---------------------------------------------------------------------------
extern "C" void kernel_launch(void* const* d_in, const int* in_sizes, int n_in,
                              void* d_out, int out_size)
{
    const float* p    = (const float*)d_in[0];
    const float* x    = (const float*)d_in[1];
    const int*   idx  = (const int*)d_in[2];
    const float* Wq   = (const float*)d_in[3];
    const float* bq   = (const float*)d_in[4];
    const float* Wk   = (const float*)d_in[5];
    const float* bk   = (const float*)d_in[6];
    const float* Wv   = (const float*)d_in[7];
    const float* bv   = (const float*)d_in[8];
    const float* pw1  = (const float*)d_in[9];
    const float* pb1  = (const float*)d_in[10];
    const float* pbng = (const float*)d_in[11];
    const float* pbnb = (const float*)d_in[12];
    const float* pbnm = (const float*)d_in[13];
    const float* pbnv = (const float*)d_in[14];
    const float* pw2  = (const float*)d_in[15];
    const float* pb2  = (const float*)d_in[16];
    const float* bn1g = (const float*)d_in[17];
    const float* bn1b = (const float*)d_in[18];
    const float* bn1m = (const float*)d_in[19];
    const float* bn1v = (const float*)d_in[20];
    const float* ww1  = (const float*)d_in[21];
    const float* wb1  = (const float*)d_in[22];
    const float* bn2g = (const float*)d_in[23];
    const float* bn2b = (const float*)d_in[24];
    const float* bn2m = (const float*)d_in[25];
    const float* bn2v = (const float*)d_in[26];
    const float* ww2  = (const float*)d_in[27];
    const float* wb2  = (const float*)d_in[28];

    int n = in_sizes[0] / 3;
    float* out = (float*)d_out;

    const int PROJ_SMEM = 70400;
    cudaFuncSetAttribute(proj3_kernel,
                         cudaFuncAttributeMaxDynamicSharedMemorySize, PROJ_SMEM);

    proj3_kernel<<<(n + 63) / 64, 256, PROJ_SMEM>>>(x, Wq, bq, Wk, bk, Wv, bv, n);
    attn_kernel<<<(n + 3) / 4, 256>>>(
        p, idx, pw1, pb1, pbng, pbnb, pbnm, pbnv, pw2, pb2,
        bn1g, bn1b, bn1m, bn1v, ww1, wb1,
        bn2g, bn2b, bn2m, bn2v, ww2, wb2,
        out, n);
}

// round 13
// speedup vs baseline: 1.8648x; 1.2307x over previous
#include <cuda_runtime.h>
#include <cuda_fp16.h>
#include <cstdint>

#define NMAX 100000
#define CDIM 64
#define NSN 16

// ---- scratch (device globals; no allocation allowed) ----
__device__ float   g_xq[NMAX * CDIM];
__device__ __half2 g_kvh[NMAX * CDIM];   // packed (k, v) per (n, c); 25.6MB -> L2-resident

// ---------------------------------------------------------------------------
// Kernel 1: q,k,v projections via fp16 mma.sync (fp32 accum).
// Block = 64 points x 64 cols, 8 warps; warp w owns cols n0=8w, all 4 m-tiles,
// all 3 matrices (B-frag per matrix, A-frag shared).
// ---------------------------------------------------------------------------
__global__ __launch_bounds__(256, 2) void proj3_kernel(
    const float* __restrict__ x,
    const float* __restrict__ Wq, const float* __restrict__ bq,
    const float* __restrict__ Wk, const float* __restrict__ bk,
    const float* __restrict__ Wv, const float* __restrict__ bv, int n)
{
    __shared__ __align__(16) __half xh[64 * 72];       // x rows fp16, stride 72
    __shared__ __align__(16) __half wh[3][64 * 72];    // W rows [c][k] fp16
    __shared__ float sbias[3][64];

    int t = threadIdx.x;
    int row0 = blockIdx.x * 64;

    // stage x tile (fp32 -> fp16), zero-padded rows
    for (int i = t; i < 2048; i += 256) {
        int r = i >> 5, kp = i & 31;
        int rr = row0 + r;
        float2 v = (rr < n) ? *(const float2*)&x[rr * 64 + kp * 2]
                            : make_float2(0.f, 0.f);
        *(__half2*)&xh[r * 72 + kp * 2] = __floats2half2_rn(v.x, v.y);
    }
    // stage W tiles (rows are output channels -> col-major B for mma)
    {
        const float* Ws[3] = { Wq, Wk, Wv };
#pragma unroll
        for (int m = 0; m < 3; m++)
            for (int i = t; i < 2048; i += 256) {
                int cc = i >> 5, kp = i & 31;
                float2 v = *(const float2*)&Ws[m][cc * 64 + kp * 2];
                *(__half2*)&wh[m][cc * 72 + kp * 2] = __floats2half2_rn(v.x, v.y);
            }
    }
    if (t < 64) { sbias[0][t] = bq[t]; sbias[1][t] = bk[t]; sbias[2][t] = bv[t]; }
    __syncthreads();

    int w = t >> 5, l = t & 31;
    int n0 = w * 8;
    int g = l >> 2, tt = l & 3;

    float acc[3][4][4];
#pragma unroll
    for (int m = 0; m < 3; m++)
#pragma unroll
        for (int mt = 0; mt < 4; mt++)
#pragma unroll
            for (int f = 0; f < 4; f++) acc[m][mt][f] = 0.f;

#pragma unroll
    for (int ks = 0; ks < 4; ks++) {
        int k0 = ks * 16 + 2 * tt;
        unsigned int bf[3][2];
#pragma unroll
        for (int m = 0; m < 3; m++) {
            const __half* Bb = &wh[m][(n0 + g) * 72];
            bf[m][0] = *(const unsigned int*)&Bb[k0];
            bf[m][1] = *(const unsigned int*)&Bb[k0 + 8];
        }
#pragma unroll
        for (int mt = 0; mt < 4; mt++) {
            const __half* Ar  = &xh[(mt * 16 + g) * 72];
            const __half* Ar8 = Ar + 8 * 72;
            unsigned int a0 = *(const unsigned int*)&Ar [k0];
            unsigned int a1 = *(const unsigned int*)&Ar8[k0];
            unsigned int a2 = *(const unsigned int*)&Ar [k0 + 8];
            unsigned int a3 = *(const unsigned int*)&Ar8[k0 + 8];
#pragma unroll
            for (int m = 0; m < 3; m++) {
                asm volatile(
                    "mma.sync.aligned.m16n8k16.row.col.f32.f16.f16.f32 "
                    "{%0,%1,%2,%3}, {%4,%5,%6,%7}, {%8,%9}, {%0,%1,%2,%3};"
                    : "+f"(acc[m][mt][0]), "+f"(acc[m][mt][1]),
                      "+f"(acc[m][mt][2]), "+f"(acc[m][mt][3])
                    : "r"(a0), "r"(a1), "r"(a2), "r"(a3),
                      "r"(bf[m][0]), "r"(bf[m][1]));
            }
        }
    }

    // epilogue: bias + writeback (q fp32, kv packed half2)
    int col = n0 + 2 * tt;
    float bq0 = sbias[0][col], bq1 = sbias[0][col + 1];
    float bk0 = sbias[1][col], bk1 = sbias[1][col + 1];
    float bv0 = sbias[2][col], bv1 = sbias[2][col + 1];
#pragma unroll
    for (int mt = 0; mt < 4; mt++) {
        int r1 = row0 + mt * 16 + g;
        int r2 = r1 + 8;
        if (r1 < n) {
            float2 q2 = make_float2(acc[0][mt][0] + bq0, acc[0][mt][1] + bq1);
            *(float2*)&g_xq[r1 * 64 + col] = q2;
            __half2 hh[2];
            hh[0] = __floats2half2_rn(acc[1][mt][0] + bk0, acc[2][mt][0] + bv0);
            hh[1] = __floats2half2_rn(acc[1][mt][1] + bk1, acc[2][mt][1] + bv1);
            *(float2*)&g_kvh[r1 * 64 + col] = *(const float2*)hh;
        }
        if (r2 < n) {
            float2 q2 = make_float2(acc[0][mt][2] + bq0, acc[0][mt][3] + bq1);
            *(float2*)&g_xq[r2 * 64 + col] = q2;
            __half2 hh[2];
            hh[0] = __floats2half2_rn(acc[1][mt][2] + bk0, acc[2][mt][2] + bv0);
            hh[1] = __floats2half2_rn(acc[1][mt][3] + bk1, acc[2][mt][3] + bv1);
            *(float2*)&g_kvh[r2 * 64 + col] = *(const float2*)hh;
        }
    }
}

// ---------------------------------------------------------------------------
// Kernel 2: fused attention (identical to R12). 4 points/block.
// B1 done as one 64x8x64 fp16 GEMM via mma.sync.m16n8k16 (warp w = point w).
// ---------------------------------------------------------------------------
__global__ __launch_bounds__(256, 4) void attn_kernel(
    const float* __restrict__ p, const int* __restrict__ idx,
    const float* __restrict__ pw1, const float* __restrict__ pb1,
    const float* __restrict__ pbng, const float* __restrict__ pbnb,
    const float* __restrict__ pbnm, const float* __restrict__ pbnv,
    const float* __restrict__ pw2, const float* __restrict__ pb2,
    const float* __restrict__ bn1g, const float* __restrict__ bn1b,
    const float* __restrict__ bn1m, const float* __restrict__ bn1v,
    const float* __restrict__ ww1, const float* __restrict__ wb1,
    const float* __restrict__ bn2g, const float* __restrict__ bn2b,
    const float* __restrict__ bn2m, const float* __restrict__ bn2v,
    const float* __restrict__ ww2, const float* __restrict__ wb2,
    float* __restrict__ out, int n)
{
    __shared__ __align__(16) __half s_wA[64 * 72];
    __shared__ __align__(16) __half s_w1h[8 * 72];
    __shared__ __align__(16) float s_u[4][16][12];
    __shared__ __align__(16) float s_lg2[4][8][20];
    __shared__ __align__(16) int   s_j[4][16];
    __shared__ __align__(16) float4 s_pr4[4][16];
    __shared__ float s_pw2[64][3];
    __shared__ float s_sc1[64], s_sh1[64], s_pb2[64];
    __shared__ __align__(16) float s_w2T[8][8];
    __shared__ float s_b1[8], s_sc2[8], s_sh2[8], s_b2[8];
    __shared__ float s_pw1[9], s_pb1[3], s_psc[3], s_psh[3];

    int t = threadIdx.x;

    if (t < 64) {
        float sc = bn1g[t] * rsqrtf(bn1v[t] + 1e-5f);
        s_sc1[t] = sc;
        s_sh1[t] = bn1b[t] - bn1m[t] * sc;
        s_pb2[t] = pb2[t];
#pragma unroll
        for (int j = 0; j < 8; j++) s_w1h[j * 72 + t] = __float2half(ww1[j * 64 + t]);
        s_pw2[t][0] = pw2[t * 3 + 0];
        s_pw2[t][1] = pw2[t * 3 + 1];
        s_pw2[t][2] = pw2[t * 3 + 2];
    } else if (t < 72) {
        int q = t - 64;
        float sc = bn2g[q] * rsqrtf(bn2v[q] + 1e-5f);
        s_sc2[q] = sc;
        s_sh2[q] = bn2b[q] - bn2m[q] * sc;
        s_b1[q] = wb1[q];
        s_b2[q] = wb2[q];
    } else if (t >= 128 && t < 192) {
        int q = t - 128;
        int k = q >> 3, j = q & 7;
        s_w2T[k][j] = ww2[j * 8 + k];
    } else if (t >= 192 && t < 207) {
        int q = t - 192;
        if (q < 9) s_pw1[q] = pw1[q];
        else if (q < 12) s_pb1[q - 9] = pb1[q - 9];
        else {
            int k = q - 12;
            float sc = pbng[k] * rsqrtf(pbnv[k] + 1e-5f);
            s_psc[k] = sc;
            s_psh[k] = pbnb[k] - pbnm[k] * sc;
        }
    }
    __syncthreads();

    int pt = t >> 6;
    int c  = t & 63;
    int l  = t & 31;
    int pid = blockIdx.x * 4 + pt;
    bool valid = pid < n;
    int n0 = valid ? pid : 0;

    if (c < 16) {
        int j = idx[n0 * 16 + c];
        s_j[pt][c] = j;
        float px = p[n0 * 3 + 0], py = p[n0 * 3 + 1], pz = p[n0 * 3 + 2];
        float dx = p[j * 3 + 0] - px;
        float dy = p[j * 3 + 1] - py;
        float dz = p[j * 3 + 2] - pz;
        float r0 = fmaf(s_pw1[0], dx, fmaf(s_pw1[1], dy, fmaf(s_pw1[2], dz, s_pb1[0])));
        float r1 = fmaf(s_pw1[3], dx, fmaf(s_pw1[4], dy, fmaf(s_pw1[5], dz, s_pb1[1])));
        float r2 = fmaf(s_pw1[6], dx, fmaf(s_pw1[7], dy, fmaf(s_pw1[8], dz, s_pb1[2])));
        float4 rr;
        rr.x = fmaxf(fmaf(r0, s_psc[0], s_psh[0]), 0.f);
        rr.y = fmaxf(fmaf(r1, s_psc[1], s_psh[1]), 0.f);
        rr.z = fmaxf(fmaf(r2, s_psc[2], s_psh[2]), 0.f);
        rr.w = 0.f;
        s_pr4[pt][c] = rr;
    }
    __syncthreads();

    float xqc = g_xq[n0 * 64 + c];
    float sc1 = s_sc1[c], sh1 = s_sh1[c];
    float w2a = s_pw2[c][0], w2b = s_pw2[c][1], w2c = s_pw2[c][2];
    float pb2c = s_pb2[c];

    float vpr[16];
#pragma unroll
    for (int hh = 0; hh < 2; hh++) {
        int js[8];
        {
            const int4* jp = (const int4*)&s_j[pt][hh * 8];
            int4 v0 = jp[0], v1 = jp[1];
            js[0] = v0.x; js[1] = v0.y; js[2] = v0.z; js[3] = v0.w;
            js[4] = v1.x; js[5] = v1.y; js[6] = v1.z; js[7] = v1.w;
        }
        __half2 kvh[8];
#pragma unroll
        for (int q = 0; q < 8; q++)
            kvh[q] = __ldcg(&g_kvh[js[q] * 64 + c]);
#pragma unroll
        for (int q = 0; q < 8; q++) {
            int nb = hh * 8 + q;
            float2 kv = __half22float2(kvh[q]);
            float4 rr = s_pr4[pt][nb];
            float pr = fmaf(w2a, rr.x, fmaf(w2b, rr.y, fmaf(w2c, rr.z, pb2c)));
            float w = kv.x - xqc + pr;
            s_wA[(pt * 16 + nb) * 72 + c] =
                __float2half(fmaxf(fmaf(w, sc1, sh1), 0.f));
            vpr[nb] = kv.y + pr;
        }
    }
    __syncthreads();

    {
        int wid = t >> 5;
        if (wid < 4) {
            int g  = l >> 2;
            int tt = l & 3;
            float c0 = 0.f, c1 = 0.f, c2 = 0.f, c3 = 0.f;
            const __half* Ab  = &s_wA[(wid * 16 + g) * 72];
            const __half* Ab8 = Ab + 8 * 72;
            const __half* Bb  = &s_w1h[g * 72];
#pragma unroll
            for (int ks = 0; ks < 4; ks++) {
                int k0 = ks * 16 + 2 * tt;
                unsigned int a0 = *(const unsigned int*)&Ab [k0];
                unsigned int a1 = *(const unsigned int*)&Ab8[k0];
                unsigned int a2 = *(const unsigned int*)&Ab [k0 + 8];
                unsigned int a3 = *(const unsigned int*)&Ab8[k0 + 8];
                unsigned int b0 = *(const unsigned int*)&Bb [k0];
                unsigned int b1 = *(const unsigned int*)&Bb [k0 + 8];
                asm volatile(
                    "mma.sync.aligned.m16n8k16.row.col.f32.f16.f16.f32 "
                    "{%0,%1,%2,%3}, {%4,%5,%6,%7}, {%8,%9}, {%0,%1,%2,%3};"
                    : "+f"(c0), "+f"(c1), "+f"(c2), "+f"(c3)
                    : "r"(a0), "r"(a1), "r"(a2), "r"(a3), "r"(b0), "r"(b1));
            }
            int j0 = 2 * tt;
            float b10 = s_b1[j0],  b11 = s_b1[j0 + 1];
            float s20 = s_sc2[j0], s21 = s_sc2[j0 + 1];
            float h20 = s_sh2[j0], h21 = s_sh2[j0 + 1];
            s_u[wid][g][j0]         = fmaxf(fmaf(c0 + b10, s20, h20), 0.f);
            s_u[wid][g][j0 + 1]     = fmaxf(fmaf(c1 + b11, s21, h21), 0.f);
            s_u[wid][g + 8][j0]     = fmaxf(fmaf(c2 + b10, s20, h20), 0.f);
            s_u[wid][g + 8][j0 + 1] = fmaxf(fmaf(c3 + b11, s21, h21), 0.f);
        }
    }
    __syncthreads();

    {
        int nb = c >> 2;
        int j0 = (c & 3) * 2;
        const float4* up = (const float4*)s_u[pt][nb];
        float4 u0 = up[0], u1 = up[1];
        float uu[8] = { u0.x, u0.y, u0.z, u0.w, u1.x, u1.y, u1.z, u1.w };
        float a0 = s_b2[j0], a1 = s_b2[j0 + 1];
#pragma unroll
        for (int k = 0; k < 8; k++) {
            float2 qv = *(const float2*)&s_w2T[k][j0];
            a0 = fmaf(uu[k], qv.x, a0);
            a1 = fmaf(uu[k], qv.y, a1);
        }
        s_lg2[pt][j0][nb]     = a0;
        s_lg2[pt][j0 + 1][nb] = a1;
    }
    __syncthreads();

    if (c < 8) {
        int j = c;
        float4 L[4];
#pragma unroll
        for (int q = 0; q < 4; q++) L[q] = *(const float4*)&s_lg2[pt][j][q * 4];
        float lv[16] = { L[0].x, L[0].y, L[0].z, L[0].w,
                         L[1].x, L[1].y, L[1].z, L[1].w,
                         L[2].x, L[2].y, L[2].z, L[2].w,
                         L[3].x, L[3].y, L[3].z, L[3].w };
        float m = -1e30f;
#pragma unroll
        for (int nb = 0; nb < 16; nb++) m = fmaxf(m, lv[nb]);
        float sum = 0.f;
#pragma unroll
        for (int nb = 0; nb < 16; nb++) {
            lv[nb] = __expf(lv[nb] - m);
            sum += lv[nb];
        }
        float inv = 1.f / sum;
#pragma unroll
        for (int q = 0; q < 4; q++) {
            float4 o;
            o.x = lv[q * 4 + 0] * inv;
            o.y = lv[q * 4 + 1] * inv;
            o.z = lv[q * 4 + 2] * inv;
            o.w = lv[q * 4 + 3] * inv;
            *(float4*)&s_lg2[pt][j][q * 4] = o;
        }
    }
    __syncthreads();

    if (valid) {
        int j = c & 7;
        float acc = 0.f;
#pragma unroll
        for (int q = 0; q < 4; q++) {
            float4 w4 = *(const float4*)&s_lg2[pt][j][q * 4];
            acc = fmaf(vpr[q * 4 + 0], w4.x, acc);
            acc = fmaf(vpr[q * 4 + 1], w4.y, acc);
            acc = fmaf(vpr[q * 4 + 2], w4.z, acc);
            acc = fmaf(vpr[q * 4 + 3], w4.w, acc);
        }
        out[pid * 64 + c] = acc;
    }
}

// ---------------------------------------------------------------------------
extern "C" void kernel_launch(void* const* d_in, const int* in_sizes, int n_in,
                              void* d_out, int out_size)
{
    const float* p    = (const float*)d_in[0];
    const float* x    = (const float*)d_in[1];
    const int*   idx  = (const int*)d_in[2];
    const float* Wq   = (const float*)d_in[3];
    const float* bq   = (const float*)d_in[4];
    const float* Wk   = (const float*)d_in[5];
    const float* bk   = (const float*)d_in[6];
    const float* Wv   = (const float*)d_in[7];
    const float* bv   = (const float*)d_in[8];
    const float* pw1  = (const float*)d_in[9];
    const float* pb1  = (const float*)d_in[10];
    const float* pbng = (const float*)d_in[11];
    const float* pbnb = (const float*)d_in[12];
    const float* pbnm = (const float*)d_in[13];
    const float* pbnv = (const float*)d_in[14];
    const float* pw2  = (const float*)d_in[15];
    const float* pb2  = (const float*)d_in[16];
    const float* bn1g = (const float*)d_in[17];
    const float* bn1b = (const float*)d_in[18];
    const float* bn1m = (const float*)d_in[19];
    const float* bn1v = (const float*)d_in[20];
    const float* ww1  = (const float*)d_in[21];
    const float* wb1  = (const float*)d_in[22];
    const float* bn2g = (const float*)d_in[23];
    const float* bn2b = (const float*)d_in[24];
    const float* bn2m = (const float*)d_in[25];
    const float* bn2v = (const float*)d_in[26];
    const float* ww2  = (const float*)d_in[27];
    const float* wb2  = (const float*)d_in[28];

    int n = in_sizes[0] / 3;
    float* out = (float*)d_out;

    proj3_kernel<<<(n + 63) / 64, 256>>>(x, Wq, bq, Wk, bk, Wv, bv, n);
    attn_kernel<<<(n + 3) / 4, 256>>>(
        p, idx, pw1, pb1, pbng, pbnb, pbnm, pbnv, pw2, pb2,
        bn1g, bn1b, bn1m, bn1v, ww1, wb1,
        bn2g, bn2b, bn2m, bn2v, ww2, wb2,
        out, n);
}

// round 14
// speedup vs baseline: 1.8821x; 1.0093x over previous
#include <cuda_runtime.h>
#include <cuda_fp16.h>
#include <cstdint>

#define NMAX 100000
#define CDIM 64
#define NSN 16

// ---- scratch (device globals; no allocation allowed) ----
__device__ float   g_xq[NMAX * CDIM];
__device__ __half2 g_kvh[NMAX * CDIM];   // packed (k, v) per (n, c); 25.6MB -> L2-resident

// ---------------------------------------------------------------------------
// Kernel 1: q,k,v projections via fp16 mma.sync (fp32 accum).
// ---------------------------------------------------------------------------
__global__ __launch_bounds__(256, 2) void proj3_kernel(
    const float* __restrict__ x,
    const float* __restrict__ Wq, const float* __restrict__ bq,
    const float* __restrict__ Wk, const float* __restrict__ bk,
    const float* __restrict__ Wv, const float* __restrict__ bv, int n)
{
    __shared__ __align__(16) __half xh[64 * 72];       // x rows fp16, stride 72
    __shared__ __align__(16) __half wh[3][64 * 72];    // W rows [c][k] fp16
    __shared__ float sbias[3][64];

    int t = threadIdx.x;
    int row0 = blockIdx.x * 64;

    for (int i = t; i < 2048; i += 256) {
        int r = i >> 5, kp = i & 31;
        int rr = row0 + r;
        float2 v = (rr < n) ? *(const float2*)&x[rr * 64 + kp * 2]
                            : make_float2(0.f, 0.f);
        *(__half2*)&xh[r * 72 + kp * 2] = __floats2half2_rn(v.x, v.y);
    }
    {
        const float* Ws[3] = { Wq, Wk, Wv };
#pragma unroll
        for (int m = 0; m < 3; m++)
            for (int i = t; i < 2048; i += 256) {
                int cc = i >> 5, kp = i & 31;
                float2 v = *(const float2*)&Ws[m][cc * 64 + kp * 2];
                *(__half2*)&wh[m][cc * 72 + kp * 2] = __floats2half2_rn(v.x, v.y);
            }
    }
    if (t < 64) { sbias[0][t] = bq[t]; sbias[1][t] = bk[t]; sbias[2][t] = bv[t]; }
    __syncthreads();

    int w = t >> 5, l = t & 31;
    int n0 = w * 8;
    int g = l >> 2, tt = l & 3;

    float acc[3][4][4];
#pragma unroll
    for (int m = 0; m < 3; m++)
#pragma unroll
        for (int mt = 0; mt < 4; mt++)
#pragma unroll
            for (int f = 0; f < 4; f++) acc[m][mt][f] = 0.f;

#pragma unroll
    for (int ks = 0; ks < 4; ks++) {
        int k0 = ks * 16 + 2 * tt;
        unsigned int bf[3][2];
#pragma unroll
        for (int m = 0; m < 3; m++) {
            const __half* Bb = &wh[m][(n0 + g) * 72];
            bf[m][0] = *(const unsigned int*)&Bb[k0];
            bf[m][1] = *(const unsigned int*)&Bb[k0 + 8];
        }
#pragma unroll
        for (int mt = 0; mt < 4; mt++) {
            const __half* Ar  = &xh[(mt * 16 + g) * 72];
            const __half* Ar8 = Ar + 8 * 72;
            unsigned int a0 = *(const unsigned int*)&Ar [k0];
            unsigned int a1 = *(const unsigned int*)&Ar8[k0];
            unsigned int a2 = *(const unsigned int*)&Ar [k0 + 8];
            unsigned int a3 = *(const unsigned int*)&Ar8[k0 + 8];
#pragma unroll
            for (int m = 0; m < 3; m++) {
                asm volatile(
                    "mma.sync.aligned.m16n8k16.row.col.f32.f16.f16.f32 "
                    "{%0,%1,%2,%3}, {%4,%5,%6,%7}, {%8,%9}, {%0,%1,%2,%3};"
                    : "+f"(acc[m][mt][0]), "+f"(acc[m][mt][1]),
                      "+f"(acc[m][mt][2]), "+f"(acc[m][mt][3])
                    : "r"(a0), "r"(a1), "r"(a2), "r"(a3),
                      "r"(bf[m][0]), "r"(bf[m][1]));
            }
        }
    }

    int col = n0 + 2 * tt;
    float bq0 = sbias[0][col], bq1 = sbias[0][col + 1];
    float bk0 = sbias[1][col], bk1 = sbias[1][col + 1];
    float bv0 = sbias[2][col], bv1 = sbias[2][col + 1];
#pragma unroll
    for (int mt = 0; mt < 4; mt++) {
        int r1 = row0 + mt * 16 + g;
        int r2 = r1 + 8;
        if (r1 < n) {
            float2 q2 = make_float2(acc[0][mt][0] + bq0, acc[0][mt][1] + bq1);
            *(float2*)&g_xq[r1 * 64 + col] = q2;
            __half2 hh[2];
            hh[0] = __floats2half2_rn(acc[1][mt][0] + bk0, acc[2][mt][0] + bv0);
            hh[1] = __floats2half2_rn(acc[1][mt][1] + bk1, acc[2][mt][1] + bv1);
            *(float2*)&g_kvh[r1 * 64 + col] = *(const float2*)hh;
        }
        if (r2 < n) {
            float2 q2 = make_float2(acc[0][mt][2] + bq0, acc[0][mt][3] + bq1);
            *(float2*)&g_xq[r2 * 64 + col] = q2;
            __half2 hh[2];
            hh[0] = __floats2half2_rn(acc[1][mt][2] + bk0, acc[2][mt][2] + bv0);
            hh[1] = __floats2half2_rn(acc[1][mt][3] + bk1, acc[2][mt][3] + bv1);
            *(float2*)&g_kvh[r2 * 64 + col] = *(const float2*)hh;
        }
    }
}

// ---------------------------------------------------------------------------
// Kernel 2: fused attention. 4 points/block. v+p_r now lives in smem (frees
// 16 regs -> 5 blocks/SM).
// ---------------------------------------------------------------------------
__global__ __launch_bounds__(256, 5) void attn_kernel(
    const float* __restrict__ p, const int* __restrict__ idx,
    const float* __restrict__ pw1, const float* __restrict__ pb1,
    const float* __restrict__ pbng, const float* __restrict__ pbnb,
    const float* __restrict__ pbnm, const float* __restrict__ pbnv,
    const float* __restrict__ pw2, const float* __restrict__ pb2,
    const float* __restrict__ bn1g, const float* __restrict__ bn1b,
    const float* __restrict__ bn1m, const float* __restrict__ bn1v,
    const float* __restrict__ ww1, const float* __restrict__ wb1,
    const float* __restrict__ bn2g, const float* __restrict__ bn2b,
    const float* __restrict__ bn2m, const float* __restrict__ bn2v,
    const float* __restrict__ ww2, const float* __restrict__ wb2,
    float* __restrict__ out, int n)
{
    __shared__ __align__(16) __half s_wA[64 * 72];
    __shared__ __align__(16) __half s_w1h[8 * 72];
    __shared__ __align__(16) float s_vbuf[4][16][68];  // v + p_r (fp32)
    __shared__ __align__(16) float s_u[4][16][12];
    __shared__ __align__(16) float s_lg2[4][8][20];
    __shared__ __align__(16) int   s_j[4][16];
    __shared__ __align__(16) float4 s_pr4[4][16];
    __shared__ float s_pw2[64][3];
    __shared__ float s_sc1[64], s_sh1[64], s_pb2[64];
    __shared__ __align__(16) float s_w2T[8][8];
    __shared__ float s_b1[8], s_sc2[8], s_sh2[8], s_b2[8];
    __shared__ float s_pw1[9], s_pb1[3], s_psc[3], s_psh[3];

    int t = threadIdx.x;

    if (t < 64) {
        float sc = bn1g[t] * rsqrtf(bn1v[t] + 1e-5f);
        s_sc1[t] = sc;
        s_sh1[t] = bn1b[t] - bn1m[t] * sc;
        s_pb2[t] = pb2[t];
#pragma unroll
        for (int j = 0; j < 8; j++) s_w1h[j * 72 + t] = __float2half(ww1[j * 64 + t]);
        s_pw2[t][0] = pw2[t * 3 + 0];
        s_pw2[t][1] = pw2[t * 3 + 1];
        s_pw2[t][2] = pw2[t * 3 + 2];
    } else if (t < 72) {
        int q = t - 64;
        float sc = bn2g[q] * rsqrtf(bn2v[q] + 1e-5f);
        s_sc2[q] = sc;
        s_sh2[q] = bn2b[q] - bn2m[q] * sc;
        s_b1[q] = wb1[q];
        s_b2[q] = wb2[q];
    } else if (t >= 128 && t < 192) {
        int q = t - 128;
        int k = q >> 3, j = q & 7;
        s_w2T[k][j] = ww2[j * 8 + k];
    } else if (t >= 192 && t < 207) {
        int q = t - 192;
        if (q < 9) s_pw1[q] = pw1[q];
        else if (q < 12) s_pb1[q - 9] = pb1[q - 9];
        else {
            int k = q - 12;
            float sc = pbng[k] * rsqrtf(pbnv[k] + 1e-5f);
            s_psc[k] = sc;
            s_psh[k] = pbnb[k] - pbnm[k] * sc;
        }
    }
    __syncthreads();

    int pt = t >> 6;
    int c  = t & 63;
    int l  = t & 31;
    int pid = blockIdx.x * 4 + pt;
    bool valid = pid < n;
    int n0 = valid ? pid : 0;

    if (c < 16) {
        int j = idx[n0 * 16 + c];
        s_j[pt][c] = j;
        float px = p[n0 * 3 + 0], py = p[n0 * 3 + 1], pz = p[n0 * 3 + 2];
        float dx = p[j * 3 + 0] - px;
        float dy = p[j * 3 + 1] - py;
        float dz = p[j * 3 + 2] - pz;
        float r0 = fmaf(s_pw1[0], dx, fmaf(s_pw1[1], dy, fmaf(s_pw1[2], dz, s_pb1[0])));
        float r1 = fmaf(s_pw1[3], dx, fmaf(s_pw1[4], dy, fmaf(s_pw1[5], dz, s_pb1[1])));
        float r2 = fmaf(s_pw1[6], dx, fmaf(s_pw1[7], dy, fmaf(s_pw1[8], dz, s_pb1[2])));
        float4 rr;
        rr.x = fmaxf(fmaf(r0, s_psc[0], s_psh[0]), 0.f);
        rr.y = fmaxf(fmaf(r1, s_psc[1], s_psh[1]), 0.f);
        rr.z = fmaxf(fmaf(r2, s_psc[2], s_psh[2]), 0.f);
        rr.w = 0.f;
        s_pr4[pt][c] = rr;
    }
    __syncthreads();

    float xqc = g_xq[n0 * 64 + c];
    float sc1 = s_sc1[c], sh1 = s_sh1[c];
    float w2a = s_pw2[c][0], w2b = s_pw2[c][1], w2c = s_pw2[c][2];
    float pb2c = s_pb2[c];

    // ---- Phase A1: gather packed (k,v); wbuf -> fp16 smem, v+pr -> fp32 smem ----
#pragma unroll
    for (int hh = 0; hh < 2; hh++) {
        int js[8];
        {
            const int4* jp = (const int4*)&s_j[pt][hh * 8];
            int4 v0 = jp[0], v1 = jp[1];
            js[0] = v0.x; js[1] = v0.y; js[2] = v0.z; js[3] = v0.w;
            js[4] = v1.x; js[5] = v1.y; js[6] = v1.z; js[7] = v1.w;
        }
        __half2 kvh[8];
#pragma unroll
        for (int q = 0; q < 8; q++)
            kvh[q] = __ldcg(&g_kvh[js[q] * 64 + c]);
#pragma unroll
        for (int q = 0; q < 8; q++) {
            int nb = hh * 8 + q;
            float2 kv = __half22float2(kvh[q]);
            float4 rr = s_pr4[pt][nb];
            float pr = fmaf(w2a, rr.x, fmaf(w2b, rr.y, fmaf(w2c, rr.z, pb2c)));
            float w = kv.x - xqc + pr;
            s_wA[(pt * 16 + nb) * 72 + c] =
                __float2half(fmaxf(fmaf(w, sc1, sh1), 0.f));
            s_vbuf[pt][nb][c] = kv.y + pr;
        }
    }
    __syncthreads();

    // ---- Phase B1: 64x8x64 GEMM via mma.sync. Warp w handles point w. ----
    {
        int wid = t >> 5;
        if (wid < 4) {
            int g  = l >> 2;
            int tt = l & 3;
            float c0 = 0.f, c1 = 0.f, c2 = 0.f, c3 = 0.f;
            const __half* Ab  = &s_wA[(wid * 16 + g) * 72];
            const __half* Ab8 = Ab + 8 * 72;
            const __half* Bb  = &s_w1h[g * 72];
#pragma unroll
            for (int ks = 0; ks < 4; ks++) {
                int k0 = ks * 16 + 2 * tt;
                unsigned int a0 = *(const unsigned int*)&Ab [k0];
                unsigned int a1 = *(const unsigned int*)&Ab8[k0];
                unsigned int a2 = *(const unsigned int*)&Ab [k0 + 8];
                unsigned int a3 = *(const unsigned int*)&Ab8[k0 + 8];
                unsigned int b0 = *(const unsigned int*)&Bb [k0];
                unsigned int b1 = *(const unsigned int*)&Bb [k0 + 8];
                asm volatile(
                    "mma.sync.aligned.m16n8k16.row.col.f32.f16.f16.f32 "
                    "{%0,%1,%2,%3}, {%4,%5,%6,%7}, {%8,%9}, {%0,%1,%2,%3};"
                    : "+f"(c0), "+f"(c1), "+f"(c2), "+f"(c3)
                    : "r"(a0), "r"(a1), "r"(a2), "r"(a3), "r"(b0), "r"(b1));
            }
            int j0 = 2 * tt;
            float b10 = s_b1[j0],  b11 = s_b1[j0 + 1];
            float s20 = s_sc2[j0], s21 = s_sc2[j0 + 1];
            float h20 = s_sh2[j0], h21 = s_sh2[j0 + 1];
            s_u[wid][g][j0]         = fmaxf(fmaf(c0 + b10, s20, h20), 0.f);
            s_u[wid][g][j0 + 1]     = fmaxf(fmaf(c1 + b11, s21, h21), 0.f);
            s_u[wid][g + 8][j0]     = fmaxf(fmaf(c2 + b10, s20, h20), 0.f);
            s_u[wid][g + 8][j0 + 1] = fmaxf(fmaf(c3 + b11, s21, h21), 0.f);
        }
    }
    __syncthreads();

    // ---- Phase B2: logits = u @ w_w2^T + b2 (written TRANSPOSED [j][nb]) ----
    {
        int nb = c >> 2;
        int j0 = (c & 3) * 2;
        const float4* up = (const float4*)s_u[pt][nb];
        float4 u0 = up[0], u1 = up[1];
        float uu[8] = { u0.x, u0.y, u0.z, u0.w, u1.x, u1.y, u1.z, u1.w };
        float a0 = s_b2[j0], a1 = s_b2[j0 + 1];
#pragma unroll
        for (int k = 0; k < 8; k++) {
            float2 qv = *(const float2*)&s_w2T[k][j0];
            a0 = fmaf(uu[k], qv.x, a0);
            a1 = fmaf(uu[k], qv.y, a1);
        }
        s_lg2[pt][j0][nb]     = a0;
        s_lg2[pt][j0 + 1][nb] = a1;
    }
    __syncthreads();

    // ---- Phase C: softmax over neighbors ----
    if (c < 8) {
        int j = c;
        float4 L[4];
#pragma unroll
        for (int q = 0; q < 4; q++) L[q] = *(const float4*)&s_lg2[pt][j][q * 4];
        float lv[16] = { L[0].x, L[0].y, L[0].z, L[0].w,
                         L[1].x, L[1].y, L[1].z, L[1].w,
                         L[2].x, L[2].y, L[2].z, L[2].w,
                         L[3].x, L[3].y, L[3].z, L[3].w };
        float m = -1e30f;
#pragma unroll
        for (int nb = 0; nb < 16; nb++) m = fmaxf(m, lv[nb]);
        float sum = 0.f;
#pragma unroll
        for (int nb = 0; nb < 16; nb++) {
            lv[nb] = __expf(lv[nb] - m);
            sum += lv[nb];
        }
        float inv = 1.f / sum;
#pragma unroll
        for (int q = 0; q < 4; q++) {
            float4 o;
            o.x = lv[q * 4 + 0] * inv;
            o.y = lv[q * 4 + 1] * inv;
            o.z = lv[q * 4 + 2] * inv;
            o.w = lv[q * 4 + 3] * inv;
            *(float4*)&s_lg2[pt][j][q * 4] = o;
        }
    }
    __syncthreads();

    // ---- Phase D: out[c] = sum_nb vbuf[nb][c] * w[j=c%8][nb] ----
    if (valid) {
        int j = c & 7;
        float acc = 0.f;
#pragma unroll
        for (int q = 0; q < 4; q++) {
            float4 w4 = *(const float4*)&s_lg2[pt][j][q * 4];
            acc = fmaf(s_vbuf[pt][q * 4 + 0][c], w4.x, acc);
            acc = fmaf(s_vbuf[pt][q * 4 + 1][c], w4.y, acc);
            acc = fmaf(s_vbuf[pt][q * 4 + 2][c], w4.z, acc);
            acc = fmaf(s_vbuf[pt][q * 4 + 3][c], w4.w, acc);
        }
        out[pid * 64 + c] = acc;
    }
}

// ---------------------------------------------------------------------------
extern "C" void kernel_launch(void* const* d_in, const int* in_sizes, int n_in,
                              void* d_out, int out_size)
{
    const float* p    = (const float*)d_in[0];
    const float* x    = (const float*)d_in[1];
    const int*   idx  = (const int*)d_in[2];
    const float* Wq   = (const float*)d_in[3];
    const float* bq   = (const float*)d_in[4];
    const float* Wk   = (const float*)d_in[5];
    const float* bk   = (const float*)d_in[6];
    const float* Wv   = (const float*)d_in[7];
    const float* bv   = (const float*)d_in[8];
    const float* pw1  = (const float*)d_in[9];
    const float* pb1  = (const float*)d_in[10];
    const float* pbng = (const float*)d_in[11];
    const float* pbnb = (const float*)d_in[12];
    const float* pbnm = (const float*)d_in[13];
    const float* pbnv = (const float*)d_in[14];
    const float* pw2  = (const float*)d_in[15];
    const float* pb2  = (const float*)d_in[16];
    const float* bn1g = (const float*)d_in[17];
    const float* bn1b = (const float*)d_in[18];
    const float* bn1m = (const float*)d_in[19];
    const float* bn1v = (const float*)d_in[20];
    const float* ww1  = (const float*)d_in[21];
    const float* wb1  = (const float*)d_in[22];
    const float* bn2g = (const float*)d_in[23];
    const float* bn2b = (const float*)d_in[24];
    const float* bn2m = (const float*)d_in[25];
    const float* bn2v = (const float*)d_in[26];
    const float* ww2  = (const float*)d_in[27];
    const float* wb2  = (const float*)d_in[28];

    int n = in_sizes[0] / 3;
    float* out = (float*)d_out;

    proj3_kernel<<<(n + 63) / 64, 256>>>(x, Wq, bq, Wk, bk, Wv, bv, n);
    attn_kernel<<<(n + 3) / 4, 256>>>(
        p, idx, pw1, pb1, pbng, pbnb, pbnm, pbnv, pw2, pb2,
        bn1g, bn1b, bn1m, bn1v, ww1, wb1,
        bn2g, bn2b, bn2m, bn2v, ww2, wb2,
        out, n);
}

// round 15
// speedup vs baseline: 1.9165x; 1.0183x over previous
#include <cuda_runtime.h>
#include <cuda_fp16.h>
#include <cstdint>

#define NMAX 100000
#define CDIM 64
#define NSN 16

// ---- scratch (device globals; no allocation allowed) ----
__device__ float   g_xq[NMAX * CDIM];
__device__ __half2 g_kvh[NMAX * CDIM];   // packed (k, v) per (n, c); 25.6MB -> L2-resident

// ---------------------------------------------------------------------------
// Kernel 1: q,k,v projections via fp16 mma.sync (fp32 accum). (unchanged R13)
// ---------------------------------------------------------------------------
__global__ __launch_bounds__(256, 2) void proj3_kernel(
    const float* __restrict__ x,
    const float* __restrict__ Wq, const float* __restrict__ bq,
    const float* __restrict__ Wk, const float* __restrict__ bk,
    const float* __restrict__ Wv, const float* __restrict__ bv, int n)
{
    __shared__ __align__(16) __half xh[64 * 72];
    __shared__ __align__(16) __half wh[3][64 * 72];
    __shared__ float sbias[3][64];

    int t = threadIdx.x;
    int row0 = blockIdx.x * 64;

    for (int i = t; i < 2048; i += 256) {
        int r = i >> 5, kp = i & 31;
        int rr = row0 + r;
        float2 v = (rr < n) ? *(const float2*)&x[rr * 64 + kp * 2]
                            : make_float2(0.f, 0.f);
        *(__half2*)&xh[r * 72 + kp * 2] = __floats2half2_rn(v.x, v.y);
    }
    {
        const float* Ws[3] = { Wq, Wk, Wv };
#pragma unroll
        for (int m = 0; m < 3; m++)
            for (int i = t; i < 2048; i += 256) {
                int cc = i >> 5, kp = i & 31;
                float2 v = *(const float2*)&Ws[m][cc * 64 + kp * 2];
                *(__half2*)&wh[m][cc * 72 + kp * 2] = __floats2half2_rn(v.x, v.y);
            }
    }
    if (t < 64) { sbias[0][t] = bq[t]; sbias[1][t] = bk[t]; sbias[2][t] = bv[t]; }
    __syncthreads();

    int w = t >> 5, l = t & 31;
    int n0 = w * 8;
    int g = l >> 2, tt = l & 3;

    float acc[3][4][4];
#pragma unroll
    for (int m = 0; m < 3; m++)
#pragma unroll
        for (int mt = 0; mt < 4; mt++)
#pragma unroll
            for (int f = 0; f < 4; f++) acc[m][mt][f] = 0.f;

#pragma unroll
    for (int ks = 0; ks < 4; ks++) {
        int k0 = ks * 16 + 2 * tt;
        unsigned int bf[3][2];
#pragma unroll
        for (int m = 0; m < 3; m++) {
            const __half* Bb = &wh[m][(n0 + g) * 72];
            bf[m][0] = *(const unsigned int*)&Bb[k0];
            bf[m][1] = *(const unsigned int*)&Bb[k0 + 8];
        }
#pragma unroll
        for (int mt = 0; mt < 4; mt++) {
            const __half* Ar  = &xh[(mt * 16 + g) * 72];
            const __half* Ar8 = Ar + 8 * 72;
            unsigned int a0 = *(const unsigned int*)&Ar [k0];
            unsigned int a1 = *(const unsigned int*)&Ar8[k0];
            unsigned int a2 = *(const unsigned int*)&Ar [k0 + 8];
            unsigned int a3 = *(const unsigned int*)&Ar8[k0 + 8];
#pragma unroll
            for (int m = 0; m < 3; m++) {
                asm volatile(
                    "mma.sync.aligned.m16n8k16.row.col.f32.f16.f16.f32 "
                    "{%0,%1,%2,%3}, {%4,%5,%6,%7}, {%8,%9}, {%0,%1,%2,%3};"
                    : "+f"(acc[m][mt][0]), "+f"(acc[m][mt][1]),
                      "+f"(acc[m][mt][2]), "+f"(acc[m][mt][3])
                    : "r"(a0), "r"(a1), "r"(a2), "r"(a3),
                      "r"(bf[m][0]), "r"(bf[m][1]));
            }
        }
    }

    int col = n0 + 2 * tt;
    float bq0 = sbias[0][col], bq1 = sbias[0][col + 1];
    float bk0 = sbias[1][col], bk1 = sbias[1][col + 1];
    float bv0 = sbias[2][col], bv1 = sbias[2][col + 1];
#pragma unroll
    for (int mt = 0; mt < 4; mt++) {
        int r1 = row0 + mt * 16 + g;
        int r2 = r1 + 8;
        if (r1 < n) {
            float2 q2 = make_float2(acc[0][mt][0] + bq0, acc[0][mt][1] + bq1);
            *(float2*)&g_xq[r1 * 64 + col] = q2;
            __half2 hh[2];
            hh[0] = __floats2half2_rn(acc[1][mt][0] + bk0, acc[2][mt][0] + bv0);
            hh[1] = __floats2half2_rn(acc[1][mt][1] + bk1, acc[2][mt][1] + bv1);
            *(float2*)&g_kvh[r1 * 64 + col] = *(const float2*)hh;
        }
        if (r2 < n) {
            float2 q2 = make_float2(acc[0][mt][2] + bq0, acc[0][mt][3] + bq1);
            *(float2*)&g_xq[r2 * 64 + col] = q2;
            __half2 hh[2];
            hh[0] = __floats2half2_rn(acc[1][mt][2] + bk0, acc[2][mt][2] + bv0);
            hh[1] = __floats2half2_rn(acc[1][mt][3] + bk1, acc[2][mt][3] + bv1);
            *(float2*)&g_kvh[r2 * 64 + col] = *(const float2*)hh;
        }
    }
}

// ---------------------------------------------------------------------------
// Kernel 2: fused attention. 4 points/block. B1 via ldmatrix + mma; B2 fused
// into the MMA-warp epilogue with quad shuffles (s_u removed, one less sync).
// ---------------------------------------------------------------------------
__global__ __launch_bounds__(256, 5) void attn_kernel(
    const float* __restrict__ p, const int* __restrict__ idx,
    const float* __restrict__ pw1, const float* __restrict__ pb1,
    const float* __restrict__ pbng, const float* __restrict__ pbnb,
    const float* __restrict__ pbnm, const float* __restrict__ pbnv,
    const float* __restrict__ pw2, const float* __restrict__ pb2,
    const float* __restrict__ bn1g, const float* __restrict__ bn1b,
    const float* __restrict__ bn1m, const float* __restrict__ bn1v,
    const float* __restrict__ ww1, const float* __restrict__ wb1,
    const float* __restrict__ bn2g, const float* __restrict__ bn2b,
    const float* __restrict__ bn2m, const float* __restrict__ bn2v,
    const float* __restrict__ ww2, const float* __restrict__ wb2,
    float* __restrict__ out, int n)
{
    __shared__ __align__(16) __half s_wA[64 * 72];
    __shared__ __align__(16) __half s_w1h[8 * 72];
    __shared__ __align__(16) float s_vbuf[4][16][68];  // v + p_r (fp32)
    __shared__ __align__(16) float s_lg2[4][8][20];    // logits TRANSPOSED [j][nb]
    __shared__ __align__(16) int   s_j[4][16];
    __shared__ __align__(16) float4 s_pr4[4][16];
    __shared__ float s_pw2[64][3];
    __shared__ float s_sc1[64], s_sh1[64], s_pb2[64];
    __shared__ __align__(16) float s_w2T[8][8];
    __shared__ float s_b1[8], s_sc2[8], s_sh2[8], s_b2[8];
    __shared__ float s_pw1[9], s_pb1[3], s_psc[3], s_psh[3];

    int t = threadIdx.x;

    if (t < 64) {
        float sc = bn1g[t] * rsqrtf(bn1v[t] + 1e-5f);
        s_sc1[t] = sc;
        s_sh1[t] = bn1b[t] - bn1m[t] * sc;
        s_pb2[t] = pb2[t];
#pragma unroll
        for (int j = 0; j < 8; j++) s_w1h[j * 72 + t] = __float2half(ww1[j * 64 + t]);
        s_pw2[t][0] = pw2[t * 3 + 0];
        s_pw2[t][1] = pw2[t * 3 + 1];
        s_pw2[t][2] = pw2[t * 3 + 2];
    } else if (t < 72) {
        int q = t - 64;
        float sc = bn2g[q] * rsqrtf(bn2v[q] + 1e-5f);
        s_sc2[q] = sc;
        s_sh2[q] = bn2b[q] - bn2m[q] * sc;
        s_b1[q] = wb1[q];
        s_b2[q] = wb2[q];
    } else if (t >= 128 && t < 192) {
        int q = t - 128;
        int k = q >> 3, j = q & 7;
        s_w2T[k][j] = ww2[j * 8 + k];
    } else if (t >= 192 && t < 207) {
        int q = t - 192;
        if (q < 9) s_pw1[q] = pw1[q];
        else if (q < 12) s_pb1[q - 9] = pb1[q - 9];
        else {
            int k = q - 12;
            float sc = pbng[k] * rsqrtf(pbnv[k] + 1e-5f);
            s_psc[k] = sc;
            s_psh[k] = pbnb[k] - pbnm[k] * sc;
        }
    }
    __syncthreads();

    int pt = t >> 6;
    int c  = t & 63;
    int l  = t & 31;
    int pid = blockIdx.x * 4 + pt;
    bool valid = pid < n;
    int n0 = valid ? pid : 0;

    if (c < 16) {
        int j = idx[n0 * 16 + c];
        s_j[pt][c] = j;
        float px = p[n0 * 3 + 0], py = p[n0 * 3 + 1], pz = p[n0 * 3 + 2];
        float dx = p[j * 3 + 0] - px;
        float dy = p[j * 3 + 1] - py;
        float dz = p[j * 3 + 2] - pz;
        float r0 = fmaf(s_pw1[0], dx, fmaf(s_pw1[1], dy, fmaf(s_pw1[2], dz, s_pb1[0])));
        float r1 = fmaf(s_pw1[3], dx, fmaf(s_pw1[4], dy, fmaf(s_pw1[5], dz, s_pb1[1])));
        float r2 = fmaf(s_pw1[6], dx, fmaf(s_pw1[7], dy, fmaf(s_pw1[8], dz, s_pb1[2])));
        float4 rr;
        rr.x = fmaxf(fmaf(r0, s_psc[0], s_psh[0]), 0.f);
        rr.y = fmaxf(fmaf(r1, s_psc[1], s_psh[1]), 0.f);
        rr.z = fmaxf(fmaf(r2, s_psc[2], s_psh[2]), 0.f);
        rr.w = 0.f;
        s_pr4[pt][c] = rr;
    }
    __syncthreads();

    float xqc = g_xq[n0 * 64 + c];
    float sc1 = s_sc1[c], sh1 = s_sh1[c];
    float w2a = s_pw2[c][0], w2b = s_pw2[c][1], w2c = s_pw2[c][2];
    float pb2c = s_pb2[c];

    // ---- Phase A1: gather packed (k,v); wbuf -> fp16 smem, v+pr -> fp32 smem ----
#pragma unroll
    for (int hh = 0; hh < 2; hh++) {
        int js[8];
        {
            const int4* jp = (const int4*)&s_j[pt][hh * 8];
            int4 v0 = jp[0], v1 = jp[1];
            js[0] = v0.x; js[1] = v0.y; js[2] = v0.z; js[3] = v0.w;
            js[4] = v1.x; js[5] = v1.y; js[6] = v1.z; js[7] = v1.w;
        }
        __half2 kvh[8];
#pragma unroll
        for (int q = 0; q < 8; q++)
            kvh[q] = __ldcg(&g_kvh[js[q] * 64 + c]);
#pragma unroll
        for (int q = 0; q < 8; q++) {
            int nb = hh * 8 + q;
            float2 kv = __half22float2(kvh[q]);
            float4 rr = s_pr4[pt][nb];
            float pr = fmaf(w2a, rr.x, fmaf(w2b, rr.y, fmaf(w2c, rr.z, pb2c)));
            float w = kv.x - xqc + pr;
            s_wA[(pt * 16 + nb) * 72 + c] =
                __float2half(fmaxf(fmaf(w, sc1, sh1), 0.f));
            s_vbuf[pt][nb][c] = kv.y + pr;
        }
    }
    __syncthreads();

    // ---- Phase B1+B2 fused: mma (ldmatrix A) + bn2/relu + logits via quad shfl ----
    {
        int wid = t >> 5;
        if (wid < 4) {
            int g  = l >> 2;
            int tt = l & 3;
            float c0 = 0.f, c1 = 0.f, c2 = 0.f, c3 = 0.f;
            const __half* Bb = &s_w1h[g * 72];
            int lrow = l & 15;
            int lcol = (l >> 4) * 8;
            const __half* Aptr = &s_wA[(wid * 16 + lrow) * 72 + lcol];
#pragma unroll
            for (int ks = 0; ks < 4; ks++) {
                unsigned int a0, a1, a2, a3;
                unsigned int saddr =
                    (unsigned int)__cvta_generic_to_shared(Aptr + ks * 16);
                asm volatile(
                    "ldmatrix.sync.aligned.m8n8.x4.shared.b16 {%0,%1,%2,%3}, [%4];"
                    : "=r"(a0), "=r"(a1), "=r"(a2), "=r"(a3) : "r"(saddr));
                int k0 = ks * 16 + 2 * tt;
                unsigned int b0 = *(const unsigned int*)&Bb[k0];
                unsigned int b1 = *(const unsigned int*)&Bb[k0 + 8];
                asm volatile(
                    "mma.sync.aligned.m16n8k16.row.col.f32.f16.f16.f32 "
                    "{%0,%1,%2,%3}, {%4,%5,%6,%7}, {%8,%9}, {%0,%1,%2,%3};"
                    : "+f"(c0), "+f"(c1), "+f"(c2), "+f"(c3)
                    : "r"(a0), "r"(a1), "r"(a2), "r"(a3), "r"(b0), "r"(b1));
            }
            int j0 = 2 * tt;
            float b10 = s_b1[j0],  b11 = s_b1[j0 + 1];
            float s20 = s_sc2[j0], s21 = s_sc2[j0 + 1];
            float h20 = s_sh2[j0], h21 = s_sh2[j0 + 1];
            float ua0 = fmaxf(fmaf(c0 + b10, s20, h20), 0.f);
            float ua1 = fmaxf(fmaf(c1 + b11, s21, h21), 0.f);
            float ub0 = fmaxf(fmaf(c2 + b10, s20, h20), 0.f);
            float ub1 = fmaxf(fmaf(c3 + b11, s21, h21), 0.f);

            // w2T rows j0, j0+1 (8 floats each)
            float4 wa0 = *(const float4*)&s_w2T[j0][0];
            float4 wa1 = *(const float4*)&s_w2T[j0][4];
            float4 wb0 = *(const float4*)&s_w2T[j0 + 1][0];
            float4 wb1 = *(const float4*)&s_w2T[j0 + 1][4];
            float W0[8] = { wa0.x, wa0.y, wa0.z, wa0.w, wa1.x, wa1.y, wa1.z, wa1.w };
            float W1[8] = { wb0.x, wb0.y, wb0.z, wb0.w, wb1.x, wb1.y, wb1.z, wb1.w };

            int jA = (tt & 1) * 4 + (tt & 2);   // this lane's final output j's
            int jB = jA + 1;
            float b2A = s_b2[jA], b2B = s_b2[jB];
            bool lo1 = (tt & 1) == 0;
            bool lo2 = (tt & 2) == 0;

#pragma unroll
            for (int rr = 0; rr < 2; rr++) {
                float u0 = rr ? ub0 : ua0;
                float u1 = rr ? ub1 : ua1;
                float P[8];
#pragma unroll
                for (int j = 0; j < 8; j++)
                    P[j] = fmaf(u0, W0[j], u1 * W1[j]);
                float Q[4];
#pragma unroll
                for (int i = 0; i < 4; i++) {
                    float snd = lo1 ? P[i + 4] : P[i];
                    float rcv = __shfl_xor_sync(0xffffffffu, snd, 1);
                    Q[i] = (lo1 ? P[i] : P[i + 4]) + rcv;
                }
                float snd0 = lo2 ? Q[2] : Q[0];
                float snd1 = lo2 ? Q[3] : Q[1];
                float r0v = __shfl_xor_sync(0xffffffffu, snd0, 2);
                float r1v = __shfl_xor_sync(0xffffffffu, snd1, 2);
                float RA = (lo2 ? Q[0] : Q[2]) + r0v;
                float RB = (lo2 ? Q[1] : Q[3]) + r1v;
                int row = g + rr * 8;
                s_lg2[wid][jA][row] = RA + b2A;
                s_lg2[wid][jB][row] = RB + b2B;
            }
        }
    }
    __syncthreads();

    // ---- Phase C: softmax over neighbors ----
    if (c < 8) {
        int j = c;
        float4 L[4];
#pragma unroll
        for (int q = 0; q < 4; q++) L[q] = *(const float4*)&s_lg2[pt][j][q * 4];
        float lv[16] = { L[0].x, L[0].y, L[0].z, L[0].w,
                         L[1].x, L[1].y, L[1].z, L[1].w,
                         L[2].x, L[2].y, L[2].z, L[2].w,
                         L[3].x, L[3].y, L[3].z, L[3].w };
        float m = -1e30f;
#pragma unroll
        for (int nb = 0; nb < 16; nb++) m = fmaxf(m, lv[nb]);
        float sum = 0.f;
#pragma unroll
        for (int nb = 0; nb < 16; nb++) {
            lv[nb] = __expf(lv[nb] - m);
            sum += lv[nb];
        }
        float inv = 1.f / sum;
#pragma unroll
        for (int q = 0; q < 4; q++) {
            float4 o;
            o.x = lv[q * 4 + 0] * inv;
            o.y = lv[q * 4 + 1] * inv;
            o.z = lv[q * 4 + 2] * inv;
            o.w = lv[q * 4 + 3] * inv;
            *(float4*)&s_lg2[pt][j][q * 4] = o;
        }
    }
    __syncthreads();

    // ---- Phase D: out[c] = sum_nb vbuf[nb][c] * w[j=c%8][nb] ----
    if (valid) {
        int j = c & 7;
        float acc = 0.f;
#pragma unroll
        for (int q = 0; q < 4; q++) {
            float4 w4 = *(const float4*)&s_lg2[pt][j][q * 4];
            acc = fmaf(s_vbuf[pt][q * 4 + 0][c], w4.x, acc);
            acc = fmaf(s_vbuf[pt][q * 4 + 1][c], w4.y, acc);
            acc = fmaf(s_vbuf[pt][q * 4 + 2][c], w4.z, acc);
            acc = fmaf(s_vbuf[pt][q * 4 + 3][c], w4.w, acc);
        }
        out[pid * 64 + c] = acc;
    }
}

// ---------------------------------------------------------------------------
extern "C" void kernel_launch(void* const* d_in, const int* in_sizes, int n_in,
                              void* d_out, int out_size)
{
    const float* p    = (const float*)d_in[0];
    const float* x    = (const float*)d_in[1];
    const int*   idx  = (const int*)d_in[2];
    const float* Wq   = (const float*)d_in[3];
    const float* bq   = (const float*)d_in[4];
    const float* Wk   = (const float*)d_in[5];
    const float* bk   = (const float*)d_in[6];
    const float* Wv   = (const float*)d_in[7];
    const float* bv   = (const float*)d_in[8];
    const float* pw1  = (const float*)d_in[9];
    const float* pb1  = (const float*)d_in[10];
    const float* pbng = (const float*)d_in[11];
    const float* pbnb = (const float*)d_in[12];
    const float* pbnm = (const float*)d_in[13];
    const float* pbnv = (const float*)d_in[14];
    const float* pw2  = (const float*)d_in[15];
    const float* pb2  = (const float*)d_in[16];
    const float* bn1g = (const float*)d_in[17];
    const float* bn1b = (const float*)d_in[18];
    const float* bn1m = (const float*)d_in[19];
    const float* bn1v = (const float*)d_in[20];
    const float* ww1  = (const float*)d_in[21];
    const float* wb1  = (const float*)d_in[22];
    const float* bn2g = (const float*)d_in[23];
    const float* bn2b = (const float*)d_in[24];
    const float* bn2m = (const float*)d_in[25];
    const float* bn2v = (const float*)d_in[26];
    const float* ww2  = (const float*)d_in[27];
    const float* wb2  = (const float*)d_in[28];

    int n = in_sizes[0] / 3;
    float* out = (float*)d_out;

    proj3_kernel<<<(n + 63) / 64, 256>>>(x, Wq, bq, Wk, bk, Wv, bv, n);
    attn_kernel<<<(n + 3) / 4, 256>>>(
        p, idx, pw1, pb1, pbng, pbnb, pbnm, pbnv, pw2, pb2,
        bn1g, bn1b, bn1m, bn1v, ww1, wb1,
        bn2g, bn2b, bn2m, bn2v, ww2, wb2,
        out, n);
}

// round 16
// speedup vs baseline: 2.0689x; 1.0795x over previous
#include <cuda_runtime.h>
#include <cuda_fp16.h>
#include <cstdint>

#define NMAX 100000
#define CDIM 64
#define NSN 16

// ---- scratch (device globals; no allocation allowed) ----
__device__ float   g_xq[NMAX * CDIM];
__device__ __half2 g_kvh[NMAX * CDIM];   // packed (k, v) per (n, c); 25.6MB -> L2-resident

// ---------------------------------------------------------------------------
// Kernel 1: q,k,v projections via fp16 mma.sync (fp32 accum).
// 128 rows/block (8 m-tiles per warp) to halve W staging traffic.
// ---------------------------------------------------------------------------
__global__ __launch_bounds__(256, 2) void proj3_kernel(
    const float* __restrict__ x,
    const float* __restrict__ Wq, const float* __restrict__ bq,
    const float* __restrict__ Wk, const float* __restrict__ bk,
    const float* __restrict__ Wv, const float* __restrict__ bv, int n)
{
    __shared__ __align__(16) __half xh[128 * 72];      // x rows fp16, stride 72
    __shared__ __align__(16) __half wh[3][64 * 72];    // W rows [c][k] fp16
    __shared__ float sbias[3][64];

    int t = threadIdx.x;
    int row0 = blockIdx.x * 128;

    for (int i = t; i < 4096; i += 256) {
        int r = i >> 5, kp = i & 31;
        int rr = row0 + r;
        float2 v = (rr < n) ? *(const float2*)&x[rr * 64 + kp * 2]
                            : make_float2(0.f, 0.f);
        *(__half2*)&xh[r * 72 + kp * 2] = __floats2half2_rn(v.x, v.y);
    }
    {
        const float* Ws[3] = { Wq, Wk, Wv };
#pragma unroll
        for (int m = 0; m < 3; m++)
            for (int i = t; i < 2048; i += 256) {
                int cc = i >> 5, kp = i & 31;
                float2 v = *(const float2*)&Ws[m][cc * 64 + kp * 2];
                *(__half2*)&wh[m][cc * 72 + kp * 2] = __floats2half2_rn(v.x, v.y);
            }
    }
    if (t < 64) { sbias[0][t] = bq[t]; sbias[1][t] = bk[t]; sbias[2][t] = bv[t]; }
    __syncthreads();

    int w = t >> 5, l = t & 31;
    int n0 = w * 8;
    int g = l >> 2, tt = l & 3;

    float acc[3][8][4];
#pragma unroll
    for (int m = 0; m < 3; m++)
#pragma unroll
        for (int mt = 0; mt < 8; mt++)
#pragma unroll
            for (int f = 0; f < 4; f++) acc[m][mt][f] = 0.f;

#pragma unroll
    for (int ks = 0; ks < 4; ks++) {
        int k0 = ks * 16 + 2 * tt;
        unsigned int bf[3][2];
#pragma unroll
        for (int m = 0; m < 3; m++) {
            const __half* Bb = &wh[m][(n0 + g) * 72];
            bf[m][0] = *(const unsigned int*)&Bb[k0];
            bf[m][1] = *(const unsigned int*)&Bb[k0 + 8];
        }
#pragma unroll
        for (int mt = 0; mt < 8; mt++) {
            const __half* Ar  = &xh[(mt * 16 + g) * 72];
            const __half* Ar8 = Ar + 8 * 72;
            unsigned int a0 = *(const unsigned int*)&Ar [k0];
            unsigned int a1 = *(const unsigned int*)&Ar8[k0];
            unsigned int a2 = *(const unsigned int*)&Ar [k0 + 8];
            unsigned int a3 = *(const unsigned int*)&Ar8[k0 + 8];
#pragma unroll
            for (int m = 0; m < 3; m++) {
                asm volatile(
                    "mma.sync.aligned.m16n8k16.row.col.f32.f16.f16.f32 "
                    "{%0,%1,%2,%3}, {%4,%5,%6,%7}, {%8,%9}, {%0,%1,%2,%3};"
                    : "+f"(acc[m][mt][0]), "+f"(acc[m][mt][1]),
                      "+f"(acc[m][mt][2]), "+f"(acc[m][mt][3])
                    : "r"(a0), "r"(a1), "r"(a2), "r"(a3),
                      "r"(bf[m][0]), "r"(bf[m][1]));
            }
        }
    }

    int col = n0 + 2 * tt;
    float bq0 = sbias[0][col], bq1 = sbias[0][col + 1];
    float bk0 = sbias[1][col], bk1 = sbias[1][col + 1];
    float bv0 = sbias[2][col], bv1 = sbias[2][col + 1];
#pragma unroll
    for (int mt = 0; mt < 8; mt++) {
        int r1 = row0 + mt * 16 + g;
        int r2 = r1 + 8;
        if (r1 < n) {
            float2 q2 = make_float2(acc[0][mt][0] + bq0, acc[0][mt][1] + bq1);
            *(float2*)&g_xq[r1 * 64 + col] = q2;
            __half2 hh[2];
            hh[0] = __floats2half2_rn(acc[1][mt][0] + bk0, acc[2][mt][0] + bv0);
            hh[1] = __floats2half2_rn(acc[1][mt][1] + bk1, acc[2][mt][1] + bv1);
            *(float2*)&g_kvh[r1 * 64 + col] = *(const float2*)hh;
        }
        if (r2 < n) {
            float2 q2 = make_float2(acc[0][mt][2] + bq0, acc[0][mt][3] + bq1);
            *(float2*)&g_xq[r2 * 64 + col] = q2;
            __half2 hh[2];
            hh[0] = __floats2half2_rn(acc[1][mt][2] + bk0, acc[2][mt][2] + bv0);
            hh[1] = __floats2half2_rn(acc[1][mt][3] + bk1, acc[2][mt][3] + bv1);
            *(float2*)&g_kvh[r2 * 64 + col] = *(const float2*)hh;
        }
    }
}

// ---------------------------------------------------------------------------
// Kernel 2: fused attention. 4 points/block. A1 uses 8B gathers, 2 ch/lane
// (warp h of a point covers neighbors [8h,8h+8) for all 64 channels).
// ---------------------------------------------------------------------------
__global__ __launch_bounds__(256, 5) void attn_kernel(
    const float* __restrict__ p, const int* __restrict__ idx,
    const float* __restrict__ pw1, const float* __restrict__ pb1,
    const float* __restrict__ pbng, const float* __restrict__ pbnb,
    const float* __restrict__ pbnm, const float* __restrict__ pbnv,
    const float* __restrict__ pw2, const float* __restrict__ pb2,
    const float* __restrict__ bn1g, const float* __restrict__ bn1b,
    const float* __restrict__ bn1m, const float* __restrict__ bn1v,
    const float* __restrict__ ww1, const float* __restrict__ wb1,
    const float* __restrict__ bn2g, const float* __restrict__ bn2b,
    const float* __restrict__ bn2m, const float* __restrict__ bn2v,
    const float* __restrict__ ww2, const float* __restrict__ wb2,
    float* __restrict__ out, int n)
{
    __shared__ __align__(16) __half s_wA[64 * 72];
    __shared__ __align__(16) __half s_w1h[8 * 72];
    __shared__ __align__(16) float s_vbuf[4][16][68];  // v + p_r (fp32)
    __shared__ __align__(16) float s_lg2[4][8][20];    // logits TRANSPOSED [j][nb]
    __shared__ __align__(16) int   s_j[4][16];
    __shared__ __align__(16) float4 s_pr4[4][16];
    __shared__ __align__(16) float s_pw2a[64];
    __shared__ __align__(16) float s_pw2b[64];
    __shared__ __align__(16) float s_pw2c[64];
    __shared__ __align__(16) float s_sc1[64];
    __shared__ __align__(16) float s_sh1[64];
    __shared__ __align__(16) float s_pb2[64];
    __shared__ __align__(16) float s_w2T[8][8];
    __shared__ float s_b1[8], s_sc2[8], s_sh2[8], s_b2[8];
    __shared__ float s_pw1[9], s_pb1[3], s_psc[3], s_psh[3];

    int t = threadIdx.x;

    if (t < 64) {
        float sc = bn1g[t] * rsqrtf(bn1v[t] + 1e-5f);
        s_sc1[t] = sc;
        s_sh1[t] = bn1b[t] - bn1m[t] * sc;
        s_pb2[t] = pb2[t];
#pragma unroll
        for (int j = 0; j < 8; j++) s_w1h[j * 72 + t] = __float2half(ww1[j * 64 + t]);
        s_pw2a[t] = pw2[t * 3 + 0];
        s_pw2b[t] = pw2[t * 3 + 1];
        s_pw2c[t] = pw2[t * 3 + 2];
    } else if (t < 72) {
        int q = t - 64;
        float sc = bn2g[q] * rsqrtf(bn2v[q] + 1e-5f);
        s_sc2[q] = sc;
        s_sh2[q] = bn2b[q] - bn2m[q] * sc;
        s_b1[q] = wb1[q];
        s_b2[q] = wb2[q];
    } else if (t >= 128 && t < 192) {
        int q = t - 128;
        int k = q >> 3, j = q & 7;
        s_w2T[k][j] = ww2[j * 8 + k];
    } else if (t >= 192 && t < 207) {
        int q = t - 192;
        if (q < 9) s_pw1[q] = pw1[q];
        else if (q < 12) s_pb1[q - 9] = pb1[q - 9];
        else {
            int k = q - 12;
            float sc = pbng[k] * rsqrtf(pbnv[k] + 1e-5f);
            s_psc[k] = sc;
            s_psh[k] = pbnb[k] - pbnm[k] * sc;
        }
    }
    __syncthreads();

    int pt = t >> 6;
    int c  = t & 63;
    int l  = t & 31;
    int pid = blockIdx.x * 4 + pt;
    bool valid = pid < n;
    int n0 = valid ? pid : 0;

    if (c < 16) {
        int j = idx[n0 * 16 + c];
        s_j[pt][c] = j;
        float px = p[n0 * 3 + 0], py = p[n0 * 3 + 1], pz = p[n0 * 3 + 2];
        float dx = p[j * 3 + 0] - px;
        float dy = p[j * 3 + 1] - py;
        float dz = p[j * 3 + 2] - pz;
        float r0 = fmaf(s_pw1[0], dx, fmaf(s_pw1[1], dy, fmaf(s_pw1[2], dz, s_pb1[0])));
        float r1 = fmaf(s_pw1[3], dx, fmaf(s_pw1[4], dy, fmaf(s_pw1[5], dz, s_pb1[1])));
        float r2 = fmaf(s_pw1[6], dx, fmaf(s_pw1[7], dy, fmaf(s_pw1[8], dz, s_pb1[2])));
        float4 rr;
        rr.x = fmaxf(fmaf(r0, s_psc[0], s_psh[0]), 0.f);
        rr.y = fmaxf(fmaf(r1, s_psc[1], s_psh[1]), 0.f);
        rr.z = fmaxf(fmaf(r2, s_psc[2], s_psh[2]), 0.f);
        rr.w = 0.f;
        s_pr4[pt][c] = rr;
    }
    __syncthreads();

    // ---- Phase A1: 8B gathers, lane cL handles channels 2cL, 2cL+1 for
    //      neighbors [8h, 8h+8) where h = which warp of the point ----
    {
        int h = (c >> 5);          // 0 or 1
        int cL = l;                // 0..31
        int c0 = 2 * cL;
        float2 xq2  = *(const float2*)&g_xq[n0 * 64 + c0];
        float2 sc1v = *(const float2*)&s_sc1[c0];
        float2 sh1v = *(const float2*)&s_sh1[c0];
        float2 pb2v = *(const float2*)&s_pb2[c0];
        float2 w2av = *(const float2*)&s_pw2a[c0];
        float2 w2bv = *(const float2*)&s_pw2b[c0];
        float2 w2cv = *(const float2*)&s_pw2c[c0];

        int js[8];
        {
            const int4* jp = (const int4*)&s_j[pt][h * 8];
            int4 v0 = jp[0], v1 = jp[1];
            js[0] = v0.x; js[1] = v0.y; js[2] = v0.z; js[3] = v0.w;
            js[4] = v1.x; js[5] = v1.y; js[6] = v1.z; js[7] = v1.w;
        }
        uint2 kk[8];
#pragma unroll
        for (int q = 0; q < 8; q++)
            kk[q] = __ldcg((const uint2*)&g_kvh[js[q] * 64 + c0]);
#pragma unroll
        for (int q = 0; q < 8; q++) {
            int nb = h * 8 + q;
            float2 kv0 = __half22float2(*(const __half2*)&kk[q].x);
            float2 kv1 = __half22float2(*(const __half2*)&kk[q].y);
            float4 rr = s_pr4[pt][nb];
            float pr0 = fmaf(w2av.x, rr.x, fmaf(w2bv.x, rr.y, fmaf(w2cv.x, rr.z, pb2v.x)));
            float pr1 = fmaf(w2av.y, rr.x, fmaf(w2bv.y, rr.y, fmaf(w2cv.y, rr.z, pb2v.y)));
            float w0 = kv0.x - xq2.x + pr0;
            float w1 = kv1.x - xq2.y + pr1;
            w0 = fmaxf(fmaf(w0, sc1v.x, sh1v.x), 0.f);
            w1 = fmaxf(fmaf(w1, sc1v.y, sh1v.y), 0.f);
            *(__half2*)&s_wA[(pt * 16 + nb) * 72 + c0] = __floats2half2_rn(w0, w1);
            *(float2*)&s_vbuf[pt][nb][c0] = make_float2(kv0.y + pr0, kv1.y + pr1);
        }
    }
    __syncthreads();

    // ---- Phase B1+B2 fused: mma (ldmatrix A) + bn2/relu + logits via quad shfl ----
    {
        int wid = t >> 5;
        if (wid < 4) {
            int g  = l >> 2;
            int tt = l & 3;
            float c0 = 0.f, c1 = 0.f, c2 = 0.f, c3 = 0.f;
            const __half* Bb = &s_w1h[g * 72];
            int lrow = l & 15;
            int lcol = (l >> 4) * 8;
            const __half* Aptr = &s_wA[(wid * 16 + lrow) * 72 + lcol];
#pragma unroll
            for (int ks = 0; ks < 4; ks++) {
                unsigned int a0, a1, a2, a3;
                unsigned int saddr =
                    (unsigned int)__cvta_generic_to_shared(Aptr + ks * 16);
                asm volatile(
                    "ldmatrix.sync.aligned.m8n8.x4.shared.b16 {%0,%1,%2,%3}, [%4];"
                    : "=r"(a0), "=r"(a1), "=r"(a2), "=r"(a3) : "r"(saddr));
                int k0 = ks * 16 + 2 * tt;
                unsigned int b0 = *(const unsigned int*)&Bb[k0];
                unsigned int b1 = *(const unsigned int*)&Bb[k0 + 8];
                asm volatile(
                    "mma.sync.aligned.m16n8k16.row.col.f32.f16.f16.f32 "
                    "{%0,%1,%2,%3}, {%4,%5,%6,%7}, {%8,%9}, {%0,%1,%2,%3};"
                    : "+f"(c0), "+f"(c1), "+f"(c2), "+f"(c3)
                    : "r"(a0), "r"(a1), "r"(a2), "r"(a3), "r"(b0), "r"(b1));
            }
            int j0 = 2 * tt;
            float b10 = s_b1[j0],  b11 = s_b1[j0 + 1];
            float s20 = s_sc2[j0], s21 = s_sc2[j0 + 1];
            float h20 = s_sh2[j0], h21 = s_sh2[j0 + 1];
            float ua0 = fmaxf(fmaf(c0 + b10, s20, h20), 0.f);
            float ua1 = fmaxf(fmaf(c1 + b11, s21, h21), 0.f);
            float ub0 = fmaxf(fmaf(c2 + b10, s20, h20), 0.f);
            float ub1 = fmaxf(fmaf(c3 + b11, s21, h21), 0.f);

            float4 wa0 = *(const float4*)&s_w2T[j0][0];
            float4 wa1 = *(const float4*)&s_w2T[j0][4];
            float4 wb0 = *(const float4*)&s_w2T[j0 + 1][0];
            float4 wb1 = *(const float4*)&s_w2T[j0 + 1][4];
            float W0[8] = { wa0.x, wa0.y, wa0.z, wa0.w, wa1.x, wa1.y, wa1.z, wa1.w };
            float W1[8] = { wb0.x, wb0.y, wb0.z, wb0.w, wb1.x, wb1.y, wb1.z, wb1.w };

            int jA = (tt & 1) * 4 + (tt & 2);
            int jB = jA + 1;
            float b2A = s_b2[jA], b2B = s_b2[jB];
            bool lo1 = (tt & 1) == 0;
            bool lo2 = (tt & 2) == 0;

#pragma unroll
            for (int rr = 0; rr < 2; rr++) {
                float u0 = rr ? ub0 : ua0;
                float u1 = rr ? ub1 : ua1;
                float P[8];
#pragma unroll
                for (int j = 0; j < 8; j++)
                    P[j] = fmaf(u0, W0[j], u1 * W1[j]);
                float Q[4];
#pragma unroll
                for (int i = 0; i < 4; i++) {
                    float snd = lo1 ? P[i + 4] : P[i];
                    float rcv = __shfl_xor_sync(0xffffffffu, snd, 1);
                    Q[i] = (lo1 ? P[i] : P[i + 4]) + rcv;
                }
                float snd0 = lo2 ? Q[2] : Q[0];
                float snd1 = lo2 ? Q[3] : Q[1];
                float r0v = __shfl_xor_sync(0xffffffffu, snd0, 2);
                float r1v = __shfl_xor_sync(0xffffffffu, snd1, 2);
                float RA = (lo2 ? Q[0] : Q[2]) + r0v;
                float RB = (lo2 ? Q[1] : Q[3]) + r1v;
                int row = g + rr * 8;
                s_lg2[wid][jA][row] = RA + b2A;
                s_lg2[wid][jB][row] = RB + b2B;
            }
        }
    }
    __syncthreads();

    // ---- Phase C: softmax over neighbors ----
    if (c < 8) {
        int j = c;
        float4 L[4];
#pragma unroll
        for (int q = 0; q < 4; q++) L[q] = *(const float4*)&s_lg2[pt][j][q * 4];
        float lv[16] = { L[0].x, L[0].y, L[0].z, L[0].w,
                         L[1].x, L[1].y, L[1].z, L[1].w,
                         L[2].x, L[2].y, L[2].z, L[2].w,
                         L[3].x, L[3].y, L[3].z, L[3].w };
        float m = -1e30f;
#pragma unroll
        for (int nb = 0; nb < 16; nb++) m = fmaxf(m, lv[nb]);
        float sum = 0.f;
#pragma unroll
        for (int nb = 0; nb < 16; nb++) {
            lv[nb] = __expf(lv[nb] - m);
            sum += lv[nb];
        }
        float inv = 1.f / sum;
#pragma unroll
        for (int q = 0; q < 4; q++) {
            float4 o;
            o.x = lv[q * 4 + 0] * inv;
            o.y = lv[q * 4 + 1] * inv;
            o.z = lv[q * 4 + 2] * inv;
            o.w = lv[q * 4 + 3] * inv;
            *(float4*)&s_lg2[pt][j][q * 4] = o;
        }
    }
    __syncthreads();

    // ---- Phase D: out[c] = sum_nb vbuf[nb][c] * w[j=c%8][nb] ----
    if (valid) {
        int j = c & 7;
        float acc = 0.f;
#pragma unroll
        for (int q = 0; q < 4; q++) {
            float4 w4 = *(const float4*)&s_lg2[pt][j][q * 4];
            acc = fmaf(s_vbuf[pt][q * 4 + 0][c], w4.x, acc);
            acc = fmaf(s_vbuf[pt][q * 4 + 1][c], w4.y, acc);
            acc = fmaf(s_vbuf[pt][q * 4 + 2][c], w4.z, acc);
            acc = fmaf(s_vbuf[pt][q * 4 + 3][c], w4.w, acc);
        }
        out[pid * 64 + c] = acc;
    }
}

// ---------------------------------------------------------------------------
extern "C" void kernel_launch(void* const* d_in, const int* in_sizes, int n_in,
                              void* d_out, int out_size)
{
    const float* p    = (const float*)d_in[0];
    const float* x    = (const float*)d_in[1];
    const int*   idx  = (const int*)d_in[2];
    const float* Wq   = (const float*)d_in[3];
    const float* bq   = (const float*)d_in[4];
    const float* Wk   = (const float*)d_in[5];
    const float* bk   = (const float*)d_in[6];
    const float* Wv   = (const float*)d_in[7];
    const float* bv   = (const float*)d_in[8];
    const float* pw1  = (const float*)d_in[9];
    const float* pb1  = (const float*)d_in[10];
    const float* pbng = (const float*)d_in[11];
    const float* pbnb = (const float*)d_in[12];
    const float* pbnm = (const float*)d_in[13];
    const float* pbnv = (const float*)d_in[14];
    const float* pw2  = (const float*)d_in[15];
    const float* pb2  = (const float*)d_in[16];
    const float* bn1g = (const float*)d_in[17];
    const float* bn1b = (const float*)d_in[18];
    const float* bn1m = (const float*)d_in[19];
    const float* bn1v = (const float*)d_in[20];
    const float* ww1  = (const float*)d_in[21];
    const float* wb1  = (const float*)d_in[22];
    const float* bn2g = (const float*)d_in[23];
    const float* bn2b = (const float*)d_in[24];
    const float* bn2m = (const float*)d_in[25];
    const float* bn2v = (const float*)d_in[26];
    const float* ww2  = (const float*)d_in[27];
    const float* wb2  = (const float*)d_in[28];

    int n = in_sizes[0] / 3;
    float* out = (float*)d_out;

    proj3_kernel<<<(n + 127) / 128, 256>>>(x, Wq, bq, Wk, bk, Wv, bv, n);
    attn_kernel<<<(n + 3) / 4, 256>>>(
        p, idx, pw1, pb1, pbng, pbnb, pbnm, pbnv, pw2, pb2,
        bn1g, bn1b, bn1m, bn1v, ww1, wb1,
        bn2g, bn2b, bn2m, bn2v, ww2, wb2,
        out, n);
}